// round 3
// baseline (speedup 1.0000x reference)
#include <cuda_runtime.h>
#include <math.h>

#define NT 8192
#define DD 1024
#define CH 512            // row-chunks for fused Sinkhorn pass
#define RPC (NT / CH)     // 16 rows per chunk

typedef unsigned long long u64;

// ---------------- scratch (device globals) ----------------
__device__ float  g_h[(size_t)NT * DD];
__device__ float  g_a[(size_t)NT * DD];
__device__ float  g_b[(size_t)NT * DD];
__device__ float  g_r[NT];
__device__ float  g_c[NT];
__device__ float2 g_p2[(size_t)CH * NT];   // (m,l) column-LSE partials

// ================= SGEMM with packed fma.rn.f32x2 =================
#define BM 128
#define BN 128
#define BK 16
#define ARL 260   // padded row length (words) for duplicated A tile
#define BRL 132   // padded row length for B tile

enum { EPI_GELU = 0, EPI_BIAS = 1, EPI_SCALE = 2 };

__device__ __forceinline__ void ffma2(u64& d, u64 a, u64 b)
{
    asm("fma.rn.f32x2 %0, %1, %2, %0;" : "+l"(d) : "l"(a), "l"(b));
}

template <int EPI, bool BT>
__global__ void __launch_bounds__(256, 2)
sgemm2(const float* __restrict__ A, const float* __restrict__ B,
       const float* __restrict__ bias, float* __restrict__ C,
       int M, int N, int K)
{
    __shared__ __align__(16) float Ad[BK][ARL];  // duplicated A pairs
    __shared__ __align__(16) float Bs[BK][BRL];

    const int tid = threadIdx.x;
    const int bm = blockIdx.y * BM, bn = blockIdx.x * BN;
    const int tx = tid & 15, ty = tid >> 4;
    const int lrow = tid >> 2;            // 0..63
    const int lcol = (tid & 3) << 2;      // 0,4,8,12
    const int brow = tid >> 5;            // 0..7
    const int bcol = (tid & 31) << 2;

    u64 acc[8][4];
#pragma unroll
    for (int i = 0; i < 8; i++)
#pragma unroll
        for (int j = 0; j < 4; j++) acc[i][j] = 0ULL;

    for (int k0 = 0; k0 < K; k0 += BK) {
#pragma unroll
        for (int r = 0; r < 2; r++) {
            int row = lrow + (r << 6);
            float4 v = *(const float4*)(A + (size_t)(bm + row) * K + k0 + lcol);
            *(float2*)&Ad[lcol + 0][2 * row] = make_float2(v.x, v.x);
            *(float2*)&Ad[lcol + 1][2 * row] = make_float2(v.y, v.y);
            *(float2*)&Ad[lcol + 2][2 * row] = make_float2(v.z, v.z);
            *(float2*)&Ad[lcol + 3][2 * row] = make_float2(v.w, v.w);
        }
        if (!BT) {
#pragma unroll
            for (int r = 0; r < 2; r++) {
                int rk = brow + (r << 3);
                *(float4*)&Bs[rk][bcol] =
                    *(const float4*)(B + (size_t)(k0 + rk) * N + bn + bcol);
            }
        } else {
            // C_ij = sum_k A_ik * B_jk ; B is [N,K] row-major
#pragma unroll
            for (int r = 0; r < 2; r++) {
                int j = lrow + (r << 6);
                float4 v = *(const float4*)(B + (size_t)(bn + j) * K + k0 + lcol);
                Bs[lcol + 0][j] = v.x;
                Bs[lcol + 1][j] = v.y;
                Bs[lcol + 2][j] = v.z;
                Bs[lcol + 3][j] = v.w;
            }
        }
        __syncthreads();

#pragma unroll
        for (int kk = 0; kk < BK; kk++) {
            u64 ap[8], bp[4];
#pragma unroll
            for (int m = 0; m < 4; m++) {
                ulonglong2 t = *(ulonglong2*)&Ad[kk][ty * 16 + m * 4];
                ap[2 * m] = t.x;
                ap[2 * m + 1] = t.y;
            }
#pragma unroll
            for (int jp = 0; jp < 4; jp++)
                bp[jp] = *(u64*)&Bs[kk][2 * tx + 32 * jp];
#pragma unroll
            for (int i = 0; i < 8; i++)
#pragma unroll
                for (int jp = 0; jp < 4; jp++)
                    ffma2(acc[i][jp], ap[i], bp[jp]);
        }
        __syncthreads();
    }

#pragma unroll
    for (int i = 0; i < 8; i++) {
        int row = bm + ty * 8 + i;
#pragma unroll
        for (int jp = 0; jp < 4; jp++) {
            int col = bn + 2 * tx + 32 * jp;
            float x0 = __uint_as_float((unsigned)(acc[i][jp] & 0xffffffffULL));
            float x1 = __uint_as_float((unsigned)(acc[i][jp] >> 32));
            if (EPI == EPI_GELU) {
                x0 += bias[col];
                x1 += bias[col + 1];
                x0 = 0.5f * x0 * (1.0f + erff(x0 * 0.70710678118654752f));
                x1 = 0.5f * x1 * (1.0f + erff(x1 * 0.70710678118654752f));
            } else if (EPI == EPI_BIAS) {
                x0 += bias[col];
                x1 += bias[col + 1];
            } else {
                x0 *= 20.0f;
                x1 *= 20.0f;
            }
            *(float2*)&C[(size_t)row * N + col] = make_float2(x0, x1);
        }
    }
}

// ================= log-domain Sinkhorn (fused row+col per pass) =============
// Sentinel -1e30 instead of -inf avoids NaN in combines.

__device__ __forceinline__ void lse_upd(float& m, float& l, float v)
{
    if (v <= m) {
        l += __expf(v - m);
    } else {
        l = fmaf(l, __expf(m - v), 1.0f);
        m = v;
    }
}

__device__ __forceinline__ void lse_comb(float& m, float& l, float m2, float l2)
{
    float nm = fmaxf(m, m2);
    l = l * __expf(m - nm) + l2 * __expf(m2 - nm);
    m = nm;
}

__device__ __forceinline__ float blk_lse(float m, float l, float* sb, int tid)
{
#pragma unroll
    for (int o = 16; o; o >>= 1) {
        float m2 = __shfl_down_sync(0xffffffffu, m, o);
        float l2 = __shfl_down_sync(0xffffffffu, l, o);
        lse_comb(m, l, m2, l2);
    }
    if ((tid & 31) == 0) { sb[(tid >> 5) * 2] = m; sb[(tid >> 5) * 2 + 1] = l; }
    __syncthreads();
    if (tid < 32) {
        float mm = (tid < 8) ? sb[tid * 2] : -1e30f;
        float ll = (tid < 8) ? sb[tid * 2 + 1] : 0.0f;
#pragma unroll
        for (int o = 4; o; o >>= 1) {
            float m2 = __shfl_down_sync(0xffffffffu, mm, o);
            float l2 = __shfl_down_sync(0xffffffffu, ll, o);
            lse_comb(mm, ll, m2, l2);
        }
        if (tid == 0) sb[32] = mm + __logf(ll);
    }
    __syncthreads();
    float r = sb[32];
    __syncthreads();
    return r;
}

__global__ void zero_c(float* __restrict__ c)
{
    c[blockIdx.x * 256 + threadIdx.x] = 0.0f;
}

// One fused iteration over a 16-row chunk: r_i = LSE_j(s_ij - c_j), then
// accumulate per-column LSE partials of (s_ij - r_i). S is read ONCE.
__global__ void __launch_bounds__(256)
sink_iter(const float* __restrict__ S, const float* __restrict__ cprev,
          float* __restrict__ r, float2* __restrict__ part)
{
    __shared__ float sb[40];
    const int tid = threadIdx.x, chunk = blockIdx.x;

    // this thread's 32 columns: 4*(tid+256q) .. +3
    float4 cj[8];
#pragma unroll
    for (int q = 0; q < 8; q++)
        cj[q] = ((const float4*)cprev)[tid + 256 * q];

    float cm[32], cl[32];
#pragma unroll
    for (int k = 0; k < 32; k++) { cm[k] = -1e30f; cl[k] = 0.0f; }

    for (int i = chunk * RPC; i < chunk * RPC + RPC; i++) {
        const float4* S4 = (const float4*)(S + (size_t)i * NT);
        float4 s[8];
        // 4 independent row-LSE chains for ILP
        float m0 = -1e30f, m1 = -1e30f, m2 = -1e30f, m3 = -1e30f;
        float l0 = 0.f, l1 = 0.f, l2 = 0.f, l3 = 0.f;
#pragma unroll
        for (int q = 0; q < 8; q++) {
            s[q] = S4[tid + 256 * q];
            lse_upd(m0, l0, s[q].x - cj[q].x);
            lse_upd(m1, l1, s[q].y - cj[q].y);
            lse_upd(m2, l2, s[q].z - cj[q].z);
            lse_upd(m3, l3, s[q].w - cj[q].w);
        }
        lse_comb(m0, l0, m1, l1);
        lse_comb(m2, l2, m3, l3);
        lse_comb(m0, l0, m2, l2);
        float ri = blk_lse(m0, l0, sb, tid);
        if (tid == 0) r[i] = ri;
#pragma unroll
        for (int q = 0; q < 8; q++) {
            lse_upd(cm[4 * q + 0], cl[4 * q + 0], s[q].x - ri);
            lse_upd(cm[4 * q + 1], cl[4 * q + 1], s[q].y - ri);
            lse_upd(cm[4 * q + 2], cl[4 * q + 2], s[q].z - ri);
            lse_upd(cm[4 * q + 3], cl[4 * q + 3], s[q].w - ri);
        }
    }
    float2* pp = part + (size_t)chunk * NT;
#pragma unroll
    for (int q = 0; q < 8; q++) {
        int j = 4 * (tid + 256 * q);
        pp[j + 0] = make_float2(cm[4 * q + 0], cl[4 * q + 0]);
        pp[j + 1] = make_float2(cm[4 * q + 1], cl[4 * q + 1]);
        pp[j + 2] = make_float2(cm[4 * q + 2], cl[4 * q + 2]);
        pp[j + 3] = make_float2(cm[4 * q + 3], cl[4 * q + 3]);
    }
}

__global__ void __launch_bounds__(256)
comb_lse(const float2* __restrict__ part, float* __restrict__ c)
{
    int j = blockIdx.x * 256 + threadIdx.x;
    float m = -1e30f, l = 0.0f;
    for (int k = 0; k < CH; k++) {
        float2 p = part[(size_t)k * NT + j];
        lse_comb(m, l, p.x, p.y);
    }
    c[j] = m + __logf(l);
}

// out = exp(s - r_i - c_j), in place
__global__ void __launch_bounds__(256)
final_exp(float* __restrict__ S, const float* __restrict__ r,
          const float* __restrict__ c)
{
    size_t idx = (size_t)blockIdx.x * 256 + threadIdx.x;  // float4 index
    int row = (int)(idx >> 11);
    int j4 = (int)(idx & 2047);
    float4 s = ((const float4*)S)[idx];
    float rv = r[row];
    float4 cc = ((const float4*)c)[j4];
    s.x = __expf(s.x - rv - cc.x);
    s.y = __expf(s.y - rv - cc.y);
    s.z = __expf(s.z - rv - cc.z);
    s.w = __expf(s.w - rv - cc.w);
    ((float4*)S)[idx] = s;
}

// ---------------- launch ----------------
extern "C" void kernel_launch(void* const* d_in, const int* in_sizes, int n_in,
                              void* d_out, int out_size)
{
    const float* emb_a = (const float*)d_in[0];
    const float* emb_b = (const float*)d_in[1];
    const float* W1    = (const float*)d_in[2];
    const float* b1    = (const float*)d_in[3];
    const float* W2    = (const float*)d_in[4];
    const float* b2    = (const float*)d_in[5];
    float* out = (float*)d_out;

    float *h, *a, *b, *r, *c;
    float2* p2;
    cudaGetSymbolAddress((void**)&h, g_h);
    cudaGetSymbolAddress((void**)&a, g_a);
    cudaGetSymbolAddress((void**)&b, g_b);
    cudaGetSymbolAddress((void**)&r, g_r);
    cudaGetSymbolAddress((void**)&c, g_c);
    cudaGetSymbolAddress((void**)&p2, g_p2);

    dim3 blk(256);
    dim3 grid_mlp(DD / BN, NT / BM);   // (8, 64)
    dim3 grid_big(NT / BN, NT / BM);   // (64, 64)

    // MLP projections
    sgemm2<EPI_GELU, false><<<grid_mlp, blk>>>(emb_a, W1, b1, h, NT, DD, DD);
    sgemm2<EPI_BIAS, false><<<grid_mlp, blk>>>(h, W2, b2, a, NT, DD, DD);
    sgemm2<EPI_GELU, false><<<grid_mlp, blk>>>(emb_b, W1, b1, h, NT, DD, DD);
    sgemm2<EPI_BIAS, false><<<grid_mlp, blk>>>(h, W2, b2, b, NT, DD, DD);
    // scores = (a @ b^T) / TEMP
    sgemm2<EPI_SCALE, true><<<grid_big, blk>>>(a, b, nullptr, out, NT, NT, DD);

    // 20 log-domain Sinkhorn iterations; S stays read-only
    zero_c<<<NT / 256, blk>>>(c);
    for (int it = 0; it < 20; it++) {
        sink_iter<<<CH, blk>>>(out, c, r, p2);
        comb_lse<<<NT / 256, blk>>>(p2, c);
    }

    final_exp<<<(unsigned)((size_t)NT * NT / 4 / 256), blk>>>(out, r, c);
}

// round 5
// speedup vs baseline: 3.0624x; 3.0624x over previous
#include <cuda_runtime.h>
#include <cuda_bf16.h>
#include <math.h>
#include <stdint.h>

#define NT 8192
#define DD 1024
#define CSPLIT 128        // iter-1 column-partial chunks
#define CH 512            // fast-iter row chunks
#define RPC (NT / CH)     // 16 rows per chunk

typedef unsigned long long u64;

// ---------------- scratch (device globals) ----------------
__device__ float  g_h[(size_t)NT * DD];
__device__ float  g_a[(size_t)NT * DD];
__device__ float  g_b[(size_t)NT * DD];
__device__ __nv_bfloat16 g_a1[(size_t)NT * DD];
__device__ __nv_bfloat16 g_a2[(size_t)NT * DD];
__device__ __nv_bfloat16 g_a3[(size_t)NT * DD];
__device__ __nv_bfloat16 g_b1[(size_t)NT * DD];
__device__ __nv_bfloat16 g_b2[(size_t)NT * DD];
__device__ __nv_bfloat16 g_b3[(size_t)NT * DD];
__device__ float  g_r[NT];
__device__ float  g_c[NT];
__device__ float  g_cz[NT];                // zeros for iter-1 row pass
__device__ float  g_p[(size_t)CH * NT];    // sum partials (fast iters)
__device__ float2 g_p2[(size_t)CSPLIT * NT];

// ================= fp32 SIMT GEMM (MLPs) =================
#define BM 128
#define BN 128
#define BK 16
#define ARL 260
#define BRL 132

enum { EPI_GELU = 0, EPI_BIAS = 1 };

__device__ __forceinline__ void ffma2(u64& d, u64 a, u64 b)
{
    asm("fma.rn.f32x2 %0, %1, %2, %0;" : "+l"(d) : "l"(a), "l"(b));
}

template <int EPI>
__global__ void __launch_bounds__(256, 2)
sgemm2(const float* __restrict__ A, const float* __restrict__ B,
       const float* __restrict__ bias, float* __restrict__ C,
       int M, int N, int K)
{
    __shared__ __align__(16) float Ad[BK][ARL];
    __shared__ __align__(16) float Bs[BK][BRL];

    const int tid = threadIdx.x;
    const int bm = blockIdx.y * BM, bn = blockIdx.x * BN;
    const int tx = tid & 15, ty = tid >> 4;
    const int lrow = tid >> 2;
    const int lcol = (tid & 3) << 2;
    const int brow = tid >> 5;
    const int bcol = (tid & 31) << 2;

    u64 acc[8][4];
#pragma unroll
    for (int i = 0; i < 8; i++)
#pragma unroll
        for (int j = 0; j < 4; j++) acc[i][j] = 0ULL;

    for (int k0 = 0; k0 < K; k0 += BK) {
#pragma unroll
        for (int r = 0; r < 2; r++) {
            int row = lrow + (r << 6);
            float4 v = *(const float4*)(A + (size_t)(bm + row) * K + k0 + lcol);
            *(float2*)&Ad[lcol + 0][2 * row] = make_float2(v.x, v.x);
            *(float2*)&Ad[lcol + 1][2 * row] = make_float2(v.y, v.y);
            *(float2*)&Ad[lcol + 2][2 * row] = make_float2(v.z, v.z);
            *(float2*)&Ad[lcol + 3][2 * row] = make_float2(v.w, v.w);
        }
#pragma unroll
        for (int r = 0; r < 2; r++) {
            int rk = brow + (r << 3);
            *(float4*)&Bs[rk][bcol] =
                *(const float4*)(B + (size_t)(k0 + rk) * N + bn + bcol);
        }
        __syncthreads();

#pragma unroll
        for (int kk = 0; kk < BK; kk++) {
            u64 ap[8], bp[4];
#pragma unroll
            for (int m = 0; m < 4; m++) {
                ulonglong2 t = *(ulonglong2*)&Ad[kk][ty * 16 + m * 4];
                ap[2 * m] = t.x;
                ap[2 * m + 1] = t.y;
            }
#pragma unroll
            for (int jp = 0; jp < 4; jp++)
                bp[jp] = *(u64*)&Bs[kk][2 * tx + 32 * jp];
#pragma unroll
            for (int i = 0; i < 8; i++)
#pragma unroll
                for (int jp = 0; jp < 4; jp++)
                    ffma2(acc[i][jp], ap[i], bp[jp]);
        }
        __syncthreads();
    }

#pragma unroll
    for (int i = 0; i < 8; i++) {
        int row = bm + ty * 8 + i;
#pragma unroll
        for (int jp = 0; jp < 4; jp++) {
            int col = bn + 2 * tx + 32 * jp;
            float x0 = __uint_as_float((unsigned)(acc[i][jp] & 0xffffffffULL));
            float x1 = __uint_as_float((unsigned)(acc[i][jp] >> 32));
            x0 += bias[col];
            x1 += bias[col + 1];
            if (EPI == EPI_GELU) {
                x0 = 0.5f * x0 * (1.0f + erff(x0 * 0.70710678118654752f));
                x1 = 0.5f * x1 * (1.0f + erff(x1 * 0.70710678118654752f));
            }
            *(float2*)&C[(size_t)row * N + col] = make_float2(x0, x1);
        }
    }
}

// ================= bf16x3 split =================
__global__ void __launch_bounds__(256)
split3(const float* __restrict__ x, __nv_bfloat16* __restrict__ o1,
       __nv_bfloat16* __restrict__ o2, __nv_bfloat16* __restrict__ o3)
{
    size_t i4 = (size_t)blockIdx.x * 256 + threadIdx.x;
    float4 v = ((const float4*)x)[i4];
    float vv[4] = {v.x, v.y, v.z, v.w};
    __nv_bfloat16 e1[4], e2[4], e3[4];
#pragma unroll
    for (int k = 0; k < 4; k++) {
        float f = vv[k];
        __nv_bfloat16 h1 = __float2bfloat16_rn(f);
        float r = f - __bfloat162float(h1);
        __nv_bfloat16 h2 = __float2bfloat16_rn(r);
        float r2 = r - __bfloat162float(h2);
        __nv_bfloat16 h3 = __float2bfloat16_rn(r2);
        e1[k] = h1; e2[k] = h2; e3[k] = h3;
    }
    ((uint2*)o1)[i4] = *(uint2*)e1;
    ((uint2*)o2)[i4] = *(uint2*)e2;
    ((uint2*)o3)[i4] = *(uint2*)e3;
}

// ================= mma.sync bf16x6 GEMM: C = (A · B^T) * 20 =================
// Tile 128x128, BK=32, 6 split tiles resident per k-chunk, double-buffered.
#define BKC 32
#define AST 40                  // padded smem stride (bf16)
#define TSZ (128 * AST)         // bf16 per tile = 5120
#define NCHK (DD / BKC)         // 32 k-chunks
#define MM_SMEM (2 * 6 * TSZ * 2)  // bytes = 122880

__device__ __forceinline__ uint32_t smem_u32(const void* p) {
    uint32_t a;
    asm("{ .reg .u64 t; cvta.to.shared.u64 t, %1; cvt.u32.u64 %0, t; }"
        : "=r"(a) : "l"(p));
    return a;
}
__device__ __forceinline__ void cp16(uint32_t dst, const void* src) {
    asm volatile("cp.async.ca.shared.global [%0], [%1], 16;"
                 :: "r"(dst), "l"(src) : "memory");
}
__device__ __forceinline__ void cp_commit() {
    asm volatile("cp.async.commit_group;" ::: "memory");
}
template <int N>
__device__ __forceinline__ void cp_wait() {
    asm volatile("cp.async.wait_group %0;" :: "n"(N) : "memory");
}
__device__ __forceinline__ void ldsm4(uint32_t& r0, uint32_t& r1,
                                      uint32_t& r2, uint32_t& r3, uint32_t a) {
    asm volatile("ldmatrix.sync.aligned.m8n8.x4.shared.b16 {%0,%1,%2,%3}, [%4];"
                 : "=r"(r0), "=r"(r1), "=r"(r2), "=r"(r3) : "r"(a));
}
__device__ __forceinline__ void mma16816(float* d, const uint32_t* a,
                                         const uint32_t* b) {
    asm volatile(
        "mma.sync.aligned.m16n8k16.row.col.f32.bf16.bf16.f32 "
        "{%0,%1,%2,%3}, {%4,%5,%6,%7}, {%8,%9}, {%0,%1,%2,%3};"
        : "+f"(d[0]), "+f"(d[1]), "+f"(d[2]), "+f"(d[3])
        : "r"(a[0]), "r"(a[1]), "r"(a[2]), "r"(a[3]), "r"(b[0]), "r"(b[1]));
}

__global__ void __launch_bounds__(256, 1)
mma_gemm(const __nv_bfloat16* __restrict__ a1, const __nv_bfloat16* __restrict__ a2,
         const __nv_bfloat16* __restrict__ a3, const __nv_bfloat16* __restrict__ b1,
         const __nv_bfloat16* __restrict__ b2, const __nv_bfloat16* __restrict__ b3,
         float* __restrict__ C)
{
    extern __shared__ __align__(16) __nv_bfloat16 sm[];
    const uint32_t sS = smem_u32(sm);
    const int tid = threadIdx.x;
    const int wid = tid >> 5, lane = tid & 31;
    const int bm = blockIdx.y * 128, bn = blockIdx.x * 128;
    const int wm = (wid & 1) * 64, wn = (wid >> 1) * 32;

    const __nv_bfloat16* tsrc[6] = {
        a1 + (size_t)bm * DD, a2 + (size_t)bm * DD, a3 + (size_t)bm * DD,
        b1 + (size_t)bn * DD, b2 + (size_t)bn * DD, b3 + (size_t)bn * DD};

    const int pa[6] = {0, 0, 1, 0, 2, 1};
    const int pb[6] = {0, 1, 0, 2, 0, 1};

    float acc[4][4][4];
#pragma unroll
    for (int i = 0; i < 4; i++)
#pragma unroll
        for (int j = 0; j < 4; j++)
#pragma unroll
            for (int k = 0; k < 4; k++) acc[i][j][k] = 0.0f;

    const int lrow = tid >> 2;         // 0..63
    const int lseg = (tid & 3) * 8;    // bf16 offset 0,8,16,24

    // prefetch chunk 0
#pragma unroll
    for (int t = 0; t < 6; t++) {
#pragma unroll
        for (int p = 0; p < 2; p++) {
            int row = lrow + p * 64;
            cp16(sS + (uint32_t)(t * TSZ + row * AST + lseg) * 2,
                 tsrc[t] + (size_t)row * DD + lseg);
        }
    }
    cp_commit();

    int buf = 0;
    for (int ch = 0; ch < NCHK; ch++) {
        if (ch + 1 < NCHK) {
            const int k0 = (ch + 1) * BKC;
            const int bo = (buf ^ 1) * 6 * TSZ;
#pragma unroll
            for (int t = 0; t < 6; t++) {
#pragma unroll
                for (int p = 0; p < 2; p++) {
                    int row = lrow + p * 64;
                    cp16(sS + (uint32_t)(bo + t * TSZ + row * AST + lseg) * 2,
                         tsrc[t] + (size_t)row * DD + k0 + lseg);
                }
            }
            cp_commit();
            cp_wait<1>();
        } else {
            cp_wait<0>();
        }
        __syncthreads();

        const int bo = buf * 6 * TSZ;
#pragma unroll
        for (int pr = 0; pr < 6; pr++) {
            const uint32_t baseA = sS + (uint32_t)(bo + pa[pr] * TSZ) * 2;
            const uint32_t baseB = sS + (uint32_t)(bo + (3 + pb[pr]) * TSZ) * 2;
#pragma unroll
            for (int kt = 0; kt < 2; kt++) {
                uint32_t af[4][4];
#pragma unroll
                for (int mt = 0; mt < 4; mt++) {
                    uint32_t addr = baseA +
                        (uint32_t)((wm + mt * 16 + (lane & 15)) * AST +
                                   kt * 16 + (lane >> 4) * 8) * 2;
                    ldsm4(af[mt][0], af[mt][1], af[mt][2], af[mt][3], addr);
                }
                uint32_t bf[2][4];
#pragma unroll
                for (int np = 0; np < 2; np++) {
                    uint32_t addr = baseB +
                        (uint32_t)((wn + np * 16 + (lane & 7) +
                                    ((lane >> 4) << 3)) * AST +
                                   kt * 16 + ((lane >> 3) & 1) * 8) * 2;
                    ldsm4(bf[np][0], bf[np][1], bf[np][2], bf[np][3], addr);
                }
#pragma unroll
                for (int mt = 0; mt < 4; mt++)
#pragma unroll
                    for (int nt = 0; nt < 4; nt++) {
                        uint32_t bb[2] = {bf[nt >> 1][(nt & 1) * 2],
                                          bf[nt >> 1][(nt & 1) * 2 + 1]};
                        mma16816(acc[mt][nt], af[mt], bb);
                    }
            }
        }
        __syncthreads();
        buf ^= 1;
    }

    // epilogue: D layout m16n8: d0,d1 -> (row l/4, col (l%4)*2); d2,d3 -> row+8
#pragma unroll
    for (int mt = 0; mt < 4; mt++) {
#pragma unroll
        for (int nt = 0; nt < 4; nt++) {
            int row = bm + wm + mt * 16 + (lane >> 2);
            int col = bn + wn + nt * 8 + (lane & 3) * 2;
            float* d = acc[mt][nt];
            *(float2*)&C[(size_t)row * NT + col] =
                make_float2(d[0] * 20.0f, d[1] * 20.0f);
            *(float2*)&C[(size_t)(row + 8) * NT + col] =
                make_float2(d[2] * 20.0f, d[3] * 20.0f);
        }
    }
}

// ================= Sinkhorn =================
__device__ __forceinline__ void lse_upd(float& m, float& l, float v)
{
    if (v <= m) {
        l += __expf(v - m);
    } else {
        l = fmaf(l, __expf(m - v), 1.0f);
        m = v;
    }
}

__global__ void zero_vec(float* __restrict__ c)
{
    c[blockIdx.x * 256 + threadIdx.x] = 0.0f;
}

// iter-1 row pass (safe online LSE)
__global__ void __launch_bounds__(256)
row_lse_kernel(const float* __restrict__ S, const float* __restrict__ c,
               float* __restrict__ r)
{
    const int row = blockIdx.x;
    const int tid = threadIdx.x;
    const float4* s4 = (const float4*)(S + (size_t)row * NT);
    const float4* c4 = (const float4*)c;

    float m = -INFINITY, l = 0.0f;
    for (int j = tid; j < NT / 4; j += 256) {
        float4 s = s4[j];
        float4 cc = c4[j];
        lse_upd(m, l, s.x - cc.x);
        lse_upd(m, l, s.y - cc.y);
        lse_upd(m, l, s.z - cc.z);
        lse_upd(m, l, s.w - cc.w);
    }

    __shared__ float sm[256], sl[256];
    sm[tid] = m; sl[tid] = l;
    __syncthreads();
    for (int s = 128; s > 0; s >>= 1) {
        if (tid < s) {
            float m2 = sm[tid + s], l2 = sl[tid + s];
            float nm = fmaxf(sm[tid], m2);
            sl[tid] = sl[tid] * __expf(sm[tid] - nm) + l2 * __expf(m2 - nm);
            sm[tid] = nm;
        }
        __syncthreads();
    }
    if (tid == 0) r[row] = sm[0] + __logf(sl[0]);
}

// iter-1 column partials (safe online LSE)
__global__ void __launch_bounds__(256)
col_lse_partial_kernel(const float* __restrict__ S, const float* __restrict__ r,
                       float2* __restrict__ part)
{
    const int j4 = blockIdx.x * blockDim.x + threadIdx.x;
    const int chunk = blockIdx.y;
    const int rowsPer = NT / CSPLIT;
    const int i0 = chunk * rowsPer;

    float m0 = -INFINITY, m1 = -INFINITY, m2 = -INFINITY, m3 = -INFINITY;
    float l0 = 0.f, l1 = 0.f, l2 = 0.f, l3 = 0.f;

    const float4* S4 = (const float4*)S;
    for (int i = i0; i < i0 + rowsPer; i++) {
        float4 s = S4[(size_t)i * (NT / 4) + j4];
        float rv = __ldg(&r[i]);
        lse_upd(m0, l0, s.x - rv);
        lse_upd(m1, l1, s.y - rv);
        lse_upd(m2, l2, s.z - rv);
        lse_upd(m3, l3, s.w - rv);
    }
    int j = j4 * 4;
    float2* p = part + (size_t)chunk * NT + j;
    p[0] = make_float2(m0, l0);
    p[1] = make_float2(m1, l1);
    p[2] = make_float2(m2, l2);
    p[3] = make_float2(m3, l3);
}

__global__ void __launch_bounds__(256)
col_lse_combine_kernel(const float2* __restrict__ part, float* __restrict__ c)
{
    const int j = blockIdx.x * blockDim.x + threadIdx.x;
    float m = -INFINITY, l = 0.0f;
    for (int k = 0; k < CSPLIT; k++) {
        float2 p = part[(size_t)k * NT + j];
        float nm = fmaxf(m, p.x);
        l = l * __expf(m - nm) + p.y * __expf(p.x - nm);
        m = nm;
    }
    c[j] = m + __logf(l);
}

__device__ __forceinline__ float blk_sum(float x, float* sb, int tid)
{
#pragma unroll
    for (int o = 16; o; o >>= 1) x += __shfl_down_sync(0xffffffffu, x, o);
    if ((tid & 31) == 0) sb[tid >> 5] = x;
    __syncthreads();
    if (tid < 32) {
        float y = (tid < 8) ? sb[tid] : 0.0f;
#pragma unroll
        for (int o = 4; o; o >>= 1) y += __shfl_down_sync(0xffffffffu, y, o);
        if (tid == 0) sb[32] = y;
    }
    __syncthreads();
    float r = sb[32];
    __syncthreads();
    return r;
}

// Fast fused iteration (iters 2..20): all exp args are <= 0 by LSE>=max,
// so no max tracking is needed. One read of S per iteration.
// Row: dot_i = sum_j exp(s - c_j - r_i);  r_i += log(dot_i)
// Col partials: acc_j += exp(s - c_j - r_new_i) = e / dot_i
__global__ void __launch_bounds__(256)
sink_fast(const float* __restrict__ S, float* __restrict__ r,
          const float* __restrict__ c, float* __restrict__ part)
{
    __shared__ float cc[NT];
    __shared__ float sb[40];
    const int tid = threadIdx.x, chunk = blockIdx.x;

    for (int k = tid; k < NT / 4; k += 256)
        ((float4*)cc)[k] = ((const float4*)c)[k];
    __syncthreads();

    float acc[32];
#pragma unroll
    for (int k = 0; k < 32; k++) acc[k] = 0.0f;

    for (int i = chunk * RPC; i < chunk * RPC + RPC; i++) {
        const float4* S4 = (const float4*)(S + (size_t)i * NT);
        const float rr = r[i];
        float4 e[8];
        float dot = 0.0f;
#pragma unroll
        for (int q = 0; q < 8; q++) {
            float4 s = S4[tid + 256 * q];
            float4 cv = *(const float4*)&cc[4 * (tid + 256 * q)];
            e[q].x = __expf(s.x - cv.x - rr);
            e[q].y = __expf(s.y - cv.y - rr);
            e[q].z = __expf(s.z - cv.z - rr);
            e[q].w = __expf(s.w - cv.w - rr);
            dot += (e[q].x + e[q].y) + (e[q].z + e[q].w);
        }
        dot = blk_sum(dot, sb, tid);
        float w = __fdividef(1.0f, dot);
        if (tid == 0) r[i] = rr + __logf(dot);
#pragma unroll
        for (int q = 0; q < 8; q++) {
            acc[4 * q + 0] = fmaf(e[q].x, w, acc[4 * q + 0]);
            acc[4 * q + 1] = fmaf(e[q].y, w, acc[4 * q + 1]);
            acc[4 * q + 2] = fmaf(e[q].z, w, acc[4 * q + 2]);
            acc[4 * q + 3] = fmaf(e[q].w, w, acc[4 * q + 3]);
        }
    }
    float* pp = part + (size_t)chunk * NT;
#pragma unroll
    for (int q = 0; q < 8; q++) {
        int j = 4 * (tid + 256 * q);
        *(float4*)&pp[j] = make_float4(acc[4 * q + 0], acc[4 * q + 1],
                                       acc[4 * q + 2], acc[4 * q + 3]);
    }
}

__global__ void __launch_bounds__(256)
comb_add(const float* __restrict__ part, float* __restrict__ c)
{
    const int j = blockIdx.x * 256 + threadIdx.x;
    float s = 0.0f;
    for (int k = 0; k < CH; k++) s += part[(size_t)k * NT + j];
    c[j] += __logf(s);
}

__global__ void __launch_bounds__(256)
final_exp_kernel(float* __restrict__ S, const float* __restrict__ r,
                 const float* __restrict__ c)
{
    size_t idx = (size_t)blockIdx.x * blockDim.x + threadIdx.x;
    int row = (int)(idx >> 11);
    int j4 = (int)(idx & 2047);
    float4 s = ((const float4*)S)[idx];
    float rv = r[row];
    float4 cc = ((const float4*)c)[j4];
    s.x = __expf(s.x - rv - cc.x);
    s.y = __expf(s.y - rv - cc.y);
    s.z = __expf(s.z - rv - cc.z);
    s.w = __expf(s.w - rv - cc.w);
    ((float4*)S)[idx] = s;
}

// ---------------- launch ----------------
extern "C" void kernel_launch(void* const* d_in, const int* in_sizes, int n_in,
                              void* d_out, int out_size)
{
    const float* emb_a = (const float*)d_in[0];
    const float* emb_b = (const float*)d_in[1];
    const float* W1    = (const float*)d_in[2];
    const float* b1    = (const float*)d_in[3];
    const float* W2    = (const float*)d_in[4];
    const float* b2    = (const float*)d_in[5];
    float* out = (float*)d_out;

    float *h, *a, *b, *r, *c, *cz, *p;
    float2* p2;
    __nv_bfloat16 *a1, *a2, *a3, *bb1, *bb2, *bb3;
    cudaGetSymbolAddress((void**)&h, g_h);
    cudaGetSymbolAddress((void**)&a, g_a);
    cudaGetSymbolAddress((void**)&b, g_b);
    cudaGetSymbolAddress((void**)&r, g_r);
    cudaGetSymbolAddress((void**)&c, g_c);
    cudaGetSymbolAddress((void**)&cz, g_cz);
    cudaGetSymbolAddress((void**)&p, g_p);
    cudaGetSymbolAddress((void**)&p2, g_p2);
    cudaGetSymbolAddress((void**)&a1, g_a1);
    cudaGetSymbolAddress((void**)&a2, g_a2);
    cudaGetSymbolAddress((void**)&a3, g_a3);
    cudaGetSymbolAddress((void**)&bb1, g_b1);
    cudaGetSymbolAddress((void**)&bb2, g_b2);
    cudaGetSymbolAddress((void**)&bb3, g_b3);

    cudaFuncSetAttribute(mma_gemm, cudaFuncAttributeMaxDynamicSharedMemorySize,
                         MM_SMEM);

    dim3 blk(256);
    dim3 grid_mlp(DD / BN, NT / BM);   // (8, 64)
    dim3 grid_big(NT / 128, NT / 128); // (64, 64)

    // MLP projections (fp32 SIMT)
    sgemm2<EPI_GELU><<<grid_mlp, blk>>>(emb_a, W1, b1, h, NT, DD, DD);
    sgemm2<EPI_BIAS><<<grid_mlp, blk>>>(h, W2, b2, a, NT, DD, DD);
    sgemm2<EPI_GELU><<<grid_mlp, blk>>>(emb_b, W1, b1, h, NT, DD, DD);
    sgemm2<EPI_BIAS><<<grid_mlp, blk>>>(h, W2, b2, b, NT, DD, DD);

    // bf16x3 splits
    unsigned nsplit = (unsigned)((size_t)NT * DD / 4 / 256);
    split3<<<nsplit, blk>>>(a, a1, a2, a3);
    split3<<<nsplit, blk>>>(b, bb1, bb2, bb3);

    // scores = (a @ b^T) * 20 via mma.sync bf16x6
    mma_gemm<<<grid_big, blk, MM_SMEM>>>(a1, a2, a3, bb1, bb2, bb3, out);

    // Sinkhorn iteration 1 (exact, overflow-safe online LSE)
    zero_vec<<<NT / 256, blk>>>(cz);
    row_lse_kernel<<<NT, blk>>>(out, cz, r);
    col_lse_partial_kernel<<<dim3((NT / 4) / 256, CSPLIT), blk>>>(out, r, p2);
    col_lse_combine_kernel<<<NT / 256, blk>>>(p2, c);

    // Iterations 2..20: fused fast path (exp args provably <= 0)
    for (int it = 0; it < 19; it++) {
        sink_fast<<<CH, blk>>>(out, r, c, p);
        comb_add<<<NT / 256, blk>>>(p, c);
    }

    final_exp_kernel<<<(unsigned)((size_t)NT * NT / 4 / 256), blk>>>(out, r, c);
}

// round 6
// speedup vs baseline: 3.3175x; 1.0833x over previous
#include <cuda_runtime.h>
#include <cuda_bf16.h>
#include <math.h>
#include <stdint.h>

#define NT 8192
#define DD 1024
#define CSPLIT 128        // iter-1 column-partial chunks
#define CH 512            // fast-iter row chunks
#define RPC (NT / CH)     // 16 rows per chunk

typedef __nv_bfloat16 bf16;

// ---------------- scratch (device globals) ----------------
__device__ bf16 g_e1[(size_t)NT * DD], g_e2[(size_t)NT * DD], g_e3[(size_t)NT * DD];
__device__ bf16 g_t1[(size_t)NT * DD], g_t2[(size_t)NT * DD], g_t3[(size_t)NT * DD];
__device__ bf16 g_a1[(size_t)NT * DD], g_a2[(size_t)NT * DD], g_a3[(size_t)NT * DD];
__device__ bf16 g_b1[(size_t)NT * DD], g_b2[(size_t)NT * DD], g_b3[(size_t)NT * DD];
__device__ bf16 g_w1a[(size_t)DD * DD], g_w1b[(size_t)DD * DD], g_w1c[(size_t)DD * DD];
__device__ bf16 g_w2a[(size_t)DD * DD], g_w2b[(size_t)DD * DD], g_w2c[(size_t)DD * DD];
__device__ float  g_r[NT];
__device__ float  g_c[NT];
__device__ float  g_cz[NT];
__device__ float  g_p[(size_t)CH * NT];
__device__ float2 g_p2[(size_t)CSPLIT * NT];

// ---------------- small helpers ----------------
__device__ __forceinline__ uint32_t smem_u32(const void* p) {
    uint32_t a;
    asm("{ .reg .u64 t; cvta.to.shared.u64 t, %1; cvt.u32.u64 %0, t; }"
        : "=r"(a) : "l"(p));
    return a;
}
__device__ __forceinline__ void cp16(uint32_t dst, const void* src) {
    asm volatile("cp.async.ca.shared.global [%0], [%1], 16;"
                 :: "r"(dst), "l"(src) : "memory");
}
__device__ __forceinline__ void cp_commit() {
    asm volatile("cp.async.commit_group;" ::: "memory");
}
template <int N>
__device__ __forceinline__ void cp_wait() {
    asm volatile("cp.async.wait_group %0;" :: "n"(N) : "memory");
}
__device__ __forceinline__ void ldsm4(uint32_t& r0, uint32_t& r1,
                                      uint32_t& r2, uint32_t& r3, uint32_t a) {
    asm volatile("ldmatrix.sync.aligned.m8n8.x4.shared.b16 {%0,%1,%2,%3}, [%4];"
                 : "=r"(r0), "=r"(r1), "=r"(r2), "=r"(r3) : "r"(a));
}
__device__ __forceinline__ void mma16816(float* d, const uint32_t* a,
                                         const uint32_t* b) {
    asm volatile(
        "mma.sync.aligned.m16n8k16.row.col.f32.bf16.bf16.f32 "
        "{%0,%1,%2,%3}, {%4,%5,%6,%7}, {%8,%9}, {%0,%1,%2,%3};"
        : "+f"(d[0]), "+f"(d[1]), "+f"(d[2]), "+f"(d[3])
        : "r"(a[0]), "r"(a[1]), "r"(a[2]), "r"(a[3]), "r"(b[0]), "r"(b[1]));
}

__device__ __forceinline__ void split1(float v, bf16& h1, bf16& h2, bf16& h3)
{
    h1 = __float2bfloat16_rn(v);
    float r = v - __bfloat162float(h1);
    h2 = __float2bfloat16_rn(r);
    float r2 = r - __bfloat162float(h2);
    h3 = __float2bfloat16_rn(r2);
}

// ================= bf16x3 split of a full fp32 array =================
__global__ void __launch_bounds__(256)
split3(const float* __restrict__ x, bf16* __restrict__ o1,
       bf16* __restrict__ o2, bf16* __restrict__ o3)
{
    size_t i4 = (size_t)blockIdx.x * 256 + threadIdx.x;
    float4 v = ((const float4*)x)[i4];
    float vv[4] = {v.x, v.y, v.z, v.w};
    bf16 e1[4], e2[4], e3[4];
#pragma unroll
    for (int k = 0; k < 4; k++) split1(vv[k], e1[k], e2[k], e3[k]);
    ((uint2*)o1)[i4] = *(uint2*)e1;
    ((uint2*)o2)[i4] = *(uint2*)e2;
    ((uint2*)o3)[i4] = *(uint2*)e3;
}

// ================= transpose + split W [K,N] -> Wt splits [N,K] ============
__global__ void __launch_bounds__(256)
tsplit(const float* __restrict__ W, bf16* __restrict__ o1,
       bf16* __restrict__ o2, bf16* __restrict__ o3)
{
    __shared__ float tile[32][33];
    const int bn = blockIdx.x * 32;   // output row = n
    const int bk = blockIdx.y * 32;   // output col = k
    const int tx = threadIdx.x, ty = threadIdx.y;   // 32 x 8
#pragma unroll
    for (int i = 0; i < 32; i += 8)
        tile[ty + i][tx] = W[(size_t)(bk + ty + i) * DD + bn + tx];
    __syncthreads();
#pragma unroll
    for (int i = 0; i < 32; i += 8) {
        float v = tile[tx][ty + i];
        bf16 h1, h2, h3;
        split1(v, h1, h2, h3);
        size_t off = (size_t)(bn + ty + i) * DD + bk + tx;
        o1[off] = h1; o2[off] = h2; o3[off] = h3;
    }
}

// ================= mma.sync bf16x6 GEMM: acc = A · B^T ======================
// Tile 128x128, BK=32, 6 split tiles resident per k-chunk, double-buffered.
// EPI_SCORE: Cf = acc * 20            (ldc = NT)
// EPI_GELU : splits of gelu(acc+bias) (ldc = DD)
// EPI_BIAS : splits of (acc+bias)     (ldc = DD)
#define BKC 32
#define AST 40
#define TSZ (128 * AST)
#define NCHK (DD / BKC)
#define MM_SMEM (2 * 6 * TSZ * 2)

enum { EPI_SCORE = 0, EPI_GELU = 1, EPI_BIAS = 2 };

template <int EPI>
__global__ void __launch_bounds__(256, 1)
mma_gemm(const bf16* __restrict__ A1, const bf16* __restrict__ A2,
         const bf16* __restrict__ A3, const bf16* __restrict__ B1,
         const bf16* __restrict__ B2, const bf16* __restrict__ B3,
         const float* __restrict__ bias, float* __restrict__ Cf,
         bf16* __restrict__ O1, bf16* __restrict__ O2, bf16* __restrict__ O3,
         int ldc)
{
    extern __shared__ __align__(16) bf16 sm[];
    const uint32_t sS = smem_u32(sm);
    const int tid = threadIdx.x;
    const int wid = tid >> 5, lane = tid & 31;
    const int bm = blockIdx.y * 128, bn = blockIdx.x * 128;
    const int wm = (wid & 1) * 64, wn = (wid >> 1) * 32;

    const bf16* tsrc[6] = {
        A1 + (size_t)bm * DD, A2 + (size_t)bm * DD, A3 + (size_t)bm * DD,
        B1 + (size_t)bn * DD, B2 + (size_t)bn * DD, B3 + (size_t)bn * DD};

    const int pa[6] = {0, 0, 1, 0, 2, 1};
    const int pb[6] = {0, 1, 0, 2, 0, 1};

    float acc[4][4][4];
#pragma unroll
    for (int i = 0; i < 4; i++)
#pragma unroll
        for (int j = 0; j < 4; j++)
#pragma unroll
            for (int k = 0; k < 4; k++) acc[i][j][k] = 0.0f;

    const int lrow = tid >> 2;
    const int lseg = (tid & 3) * 8;

#pragma unroll
    for (int t = 0; t < 6; t++) {
#pragma unroll
        for (int p = 0; p < 2; p++) {
            int row = lrow + p * 64;
            cp16(sS + (uint32_t)(t * TSZ + row * AST + lseg) * 2,
                 tsrc[t] + (size_t)row * DD + lseg);
        }
    }
    cp_commit();

    int buf = 0;
    for (int ch = 0; ch < NCHK; ch++) {
        if (ch + 1 < NCHK) {
            const int k0 = (ch + 1) * BKC;
            const int bo = (buf ^ 1) * 6 * TSZ;
#pragma unroll
            for (int t = 0; t < 6; t++) {
#pragma unroll
                for (int p = 0; p < 2; p++) {
                    int row = lrow + p * 64;
                    cp16(sS + (uint32_t)(bo + t * TSZ + row * AST + lseg) * 2,
                         tsrc[t] + (size_t)row * DD + k0 + lseg);
                }
            }
            cp_commit();
            cp_wait<1>();
        } else {
            cp_wait<0>();
        }
        __syncthreads();

        const int bo = buf * 6 * TSZ;
#pragma unroll
        for (int pr = 0; pr < 6; pr++) {
            const uint32_t baseA = sS + (uint32_t)(bo + pa[pr] * TSZ) * 2;
            const uint32_t baseB = sS + (uint32_t)(bo + (3 + pb[pr]) * TSZ) * 2;
#pragma unroll
            for (int kt = 0; kt < 2; kt++) {
                uint32_t af[4][4];
#pragma unroll
                for (int mt = 0; mt < 4; mt++) {
                    uint32_t addr = baseA +
                        (uint32_t)((wm + mt * 16 + (lane & 15)) * AST +
                                   kt * 16 + (lane >> 4) * 8) * 2;
                    ldsm4(af[mt][0], af[mt][1], af[mt][2], af[mt][3], addr);
                }
                uint32_t bfr[2][4];
#pragma unroll
                for (int np = 0; np < 2; np++) {
                    uint32_t addr = baseB +
                        (uint32_t)((wn + np * 16 + (lane & 7) +
                                    ((lane >> 4) << 3)) * AST +
                                   kt * 16 + ((lane >> 3) & 1) * 8) * 2;
                    ldsm4(bfr[np][0], bfr[np][1], bfr[np][2], bfr[np][3], addr);
                }
#pragma unroll
                for (int mt = 0; mt < 4; mt++)
#pragma unroll
                    for (int nt = 0; nt < 4; nt++) {
                        uint32_t bb[2] = {bfr[nt >> 1][(nt & 1) * 2],
                                          bfr[nt >> 1][(nt & 1) * 2 + 1]};
                        mma16816(acc[mt][nt], af[mt], bb);
                    }
            }
        }
        __syncthreads();
        buf ^= 1;
    }

    // epilogue
#pragma unroll
    for (int mt = 0; mt < 4; mt++) {
#pragma unroll
        for (int nt = 0; nt < 4; nt++) {
            int row = bm + wm + mt * 16 + (lane >> 2);
            int col = bn + wn + nt * 8 + (lane & 3) * 2;
            float* d = acc[mt][nt];
            if (EPI == EPI_SCORE) {
                *(float2*)&Cf[(size_t)row * ldc + col] =
                    make_float2(d[0] * 20.0f, d[1] * 20.0f);
                *(float2*)&Cf[(size_t)(row + 8) * ldc + col] =
                    make_float2(d[2] * 20.0f, d[3] * 20.0f);
            } else {
                float bx = bias[col], by = bias[col + 1];
                float v[4] = {d[0] + bx, d[1] + by, d[2] + bx, d[3] + by};
                if (EPI == EPI_GELU) {
#pragma unroll
                    for (int k = 0; k < 4; k++)
                        v[k] = 0.5f * v[k] *
                               (1.0f + erff(v[k] * 0.70710678118654752f));
                }
#pragma unroll
                for (int h = 0; h < 2; h++) {   // h=0: row, h=1: row+8
                    bf16 s1[2], s2[2], s3[2];
                    split1(v[2 * h + 0], s1[0], s2[0], s3[0]);
                    split1(v[2 * h + 1], s1[1], s2[1], s3[1]);
                    size_t off = (size_t)(row + 8 * h) * ldc + col;
                    *(uint32_t*)(O1 + off) = *(uint32_t*)s1;
                    *(uint32_t*)(O2 + off) = *(uint32_t*)s2;
                    *(uint32_t*)(O3 + off) = *(uint32_t*)s3;
                }
            }
        }
    }
}

// ================= Sinkhorn (R5-proven) =================
__device__ __forceinline__ void lse_upd(float& m, float& l, float v)
{
    if (v <= m) {
        l += __expf(v - m);
    } else {
        l = fmaf(l, __expf(m - v), 1.0f);
        m = v;
    }
}

__global__ void zero_vec(float* __restrict__ c)
{
    c[blockIdx.x * 256 + threadIdx.x] = 0.0f;
}

__global__ void __launch_bounds__(256)
row_lse_kernel(const float* __restrict__ S, const float* __restrict__ c,
               float* __restrict__ r)
{
    const int row = blockIdx.x;
    const int tid = threadIdx.x;
    const float4* s4 = (const float4*)(S + (size_t)row * NT);
    const float4* c4 = (const float4*)c;

    float m = -INFINITY, l = 0.0f;
    for (int j = tid; j < NT / 4; j += 256) {
        float4 s = s4[j];
        float4 cc = c4[j];
        lse_upd(m, l, s.x - cc.x);
        lse_upd(m, l, s.y - cc.y);
        lse_upd(m, l, s.z - cc.z);
        lse_upd(m, l, s.w - cc.w);
    }

    __shared__ float sm[256], sl[256];
    sm[tid] = m; sl[tid] = l;
    __syncthreads();
    for (int s = 128; s > 0; s >>= 1) {
        if (tid < s) {
            float m2 = sm[tid + s], l2 = sl[tid + s];
            float nm = fmaxf(sm[tid], m2);
            sl[tid] = sl[tid] * __expf(sm[tid] - nm) + l2 * __expf(m2 - nm);
            sm[tid] = nm;
        }
        __syncthreads();
    }
    if (tid == 0) r[row] = sm[0] + __logf(sl[0]);
}

__global__ void __launch_bounds__(256)
col_lse_partial_kernel(const float* __restrict__ S, const float* __restrict__ r,
                       float2* __restrict__ part)
{
    const int j4 = blockIdx.x * blockDim.x + threadIdx.x;
    const int chunk = blockIdx.y;
    const int rowsPer = NT / CSPLIT;
    const int i0 = chunk * rowsPer;

    float m0 = -INFINITY, m1 = -INFINITY, m2 = -INFINITY, m3 = -INFINITY;
    float l0 = 0.f, l1 = 0.f, l2 = 0.f, l3 = 0.f;

    const float4* S4 = (const float4*)S;
    for (int i = i0; i < i0 + rowsPer; i++) {
        float4 s = S4[(size_t)i * (NT / 4) + j4];
        float rv = __ldg(&r[i]);
        lse_upd(m0, l0, s.x - rv);
        lse_upd(m1, l1, s.y - rv);
        lse_upd(m2, l2, s.z - rv);
        lse_upd(m3, l3, s.w - rv);
    }
    int j = j4 * 4;
    float2* p = part + (size_t)chunk * NT + j;
    p[0] = make_float2(m0, l0);
    p[1] = make_float2(m1, l1);
    p[2] = make_float2(m2, l2);
    p[3] = make_float2(m3, l3);
}

__global__ void __launch_bounds__(256)
col_lse_combine_kernel(const float2* __restrict__ part, float* __restrict__ c)
{
    const int j = blockIdx.x * blockDim.x + threadIdx.x;
    float m = -INFINITY, l = 0.0f;
    for (int k = 0; k < CSPLIT; k++) {
        float2 p = part[(size_t)k * NT + j];
        float nm = fmaxf(m, p.x);
        l = l * __expf(m - nm) + p.y * __expf(p.x - nm);
        m = nm;
    }
    c[j] = m + __logf(l);
}

__device__ __forceinline__ float blk_sum(float x, float* sb, int tid)
{
#pragma unroll
    for (int o = 16; o; o >>= 1) x += __shfl_down_sync(0xffffffffu, x, o);
    if ((tid & 31) == 0) sb[tid >> 5] = x;
    __syncthreads();
    if (tid < 32) {
        float y = (tid < 8) ? sb[tid] : 0.0f;
#pragma unroll
        for (int o = 4; o; o >>= 1) y += __shfl_down_sync(0xffffffffu, y, o);
        if (tid == 0) sb[32] = y;
    }
    __syncthreads();
    float r = sb[32];
    __syncthreads();
    return r;
}

__global__ void __launch_bounds__(256)
sink_fast(const float* __restrict__ S, float* __restrict__ r,
          const float* __restrict__ c, float* __restrict__ part)
{
    __shared__ float cc[NT];
    __shared__ float sb[40];
    const int tid = threadIdx.x, chunk = blockIdx.x;

    for (int k = tid; k < NT / 4; k += 256)
        ((float4*)cc)[k] = ((const float4*)c)[k];
    __syncthreads();

    float acc[32];
#pragma unroll
    for (int k = 0; k < 32; k++) acc[k] = 0.0f;

    for (int i = chunk * RPC; i < chunk * RPC + RPC; i++) {
        const float4* S4 = (const float4*)(S + (size_t)i * NT);
        const float rr = r[i];
        float4 e[8];
        float dot = 0.0f;
#pragma unroll
        for (int q = 0; q < 8; q++) {
            float4 s = S4[tid + 256 * q];
            float4 cv = *(const float4*)&cc[4 * (tid + 256 * q)];
            e[q].x = __expf(s.x - cv.x - rr);
            e[q].y = __expf(s.y - cv.y - rr);
            e[q].z = __expf(s.z - cv.z - rr);
            e[q].w = __expf(s.w - cv.w - rr);
            dot += (e[q].x + e[q].y) + (e[q].z + e[q].w);
        }
        dot = blk_sum(dot, sb, tid);
        float w = __fdividef(1.0f, dot);
        if (tid == 0) r[i] = rr + __logf(dot);
#pragma unroll
        for (int q = 0; q < 8; q++) {
            acc[4 * q + 0] = fmaf(e[q].x, w, acc[4 * q + 0]);
            acc[4 * q + 1] = fmaf(e[q].y, w, acc[4 * q + 1]);
            acc[4 * q + 2] = fmaf(e[q].z, w, acc[4 * q + 2]);
            acc[4 * q + 3] = fmaf(e[q].w, w, acc[4 * q + 3]);
        }
    }
    float* pp = part + (size_t)chunk * NT;
#pragma unroll
    for (int q = 0; q < 8; q++) {
        int j = 4 * (tid + 256 * q);
        *(float4*)&pp[j] = make_float4(acc[4 * q + 0], acc[4 * q + 1],
                                       acc[4 * q + 2], acc[4 * q + 3]);
    }
}

__global__ void __launch_bounds__(256)
comb_add(const float* __restrict__ part, float* __restrict__ c)
{
    const int j = blockIdx.x * 256 + threadIdx.x;
    float s = 0.0f;
    for (int k = 0; k < CH; k++) s += part[(size_t)k * NT + j];
    c[j] += __logf(s);
}

__global__ void __launch_bounds__(256)
final_exp_kernel(float* __restrict__ S, const float* __restrict__ r,
                 const float* __restrict__ c)
{
    size_t idx = (size_t)blockIdx.x * blockDim.x + threadIdx.x;
    int row = (int)(idx >> 11);
    int j4 = (int)(idx & 2047);
    float4 s = ((const float4*)S)[idx];
    float rv = r[row];
    float4 cc = ((const float4*)c)[j4];
    s.x = __expf(s.x - rv - cc.x);
    s.y = __expf(s.y - rv - cc.y);
    s.z = __expf(s.z - rv - cc.z);
    s.w = __expf(s.w - rv - cc.w);
    ((float4*)S)[idx] = s;
}

// ---------------- launch ----------------
extern "C" void kernel_launch(void* const* d_in, const int* in_sizes, int n_in,
                              void* d_out, int out_size)
{
    const float* emb_a = (const float*)d_in[0];
    const float* emb_b = (const float*)d_in[1];
    const float* W1    = (const float*)d_in[2];
    const float* b1    = (const float*)d_in[3];
    const float* W2    = (const float*)d_in[4];
    const float* b2    = (const float*)d_in[5];
    float* out = (float*)d_out;

    float *r, *c, *cz, *p;
    float2* p2;
    bf16 *e1, *e2, *e3, *t1, *t2, *t3;
    bf16 *a1, *a2, *a3, *bb1, *bb2, *bb3;
    bf16 *w1a, *w1b, *w1c, *w2a, *w2b, *w2c;
    cudaGetSymbolAddress((void**)&r, g_r);
    cudaGetSymbolAddress((void**)&c, g_c);
    cudaGetSymbolAddress((void**)&cz, g_cz);
    cudaGetSymbolAddress((void**)&p, g_p);
    cudaGetSymbolAddress((void**)&p2, g_p2);
    cudaGetSymbolAddress((void**)&e1, g_e1);
    cudaGetSymbolAddress((void**)&e2, g_e2);
    cudaGetSymbolAddress((void**)&e3, g_e3);
    cudaGetSymbolAddress((void**)&t1, g_t1);
    cudaGetSymbolAddress((void**)&t2, g_t2);
    cudaGetSymbolAddress((void**)&t3, g_t3);
    cudaGetSymbolAddress((void**)&a1, g_a1);
    cudaGetSymbolAddress((void**)&a2, g_a2);
    cudaGetSymbolAddress((void**)&a3, g_a3);
    cudaGetSymbolAddress((void**)&bb1, g_b1);
    cudaGetSymbolAddress((void**)&bb2, g_b2);
    cudaGetSymbolAddress((void**)&bb3, g_b3);
    cudaGetSymbolAddress((void**)&w1a, g_w1a);
    cudaGetSymbolAddress((void**)&w1b, g_w1b);
    cudaGetSymbolAddress((void**)&w1c, g_w1c);
    cudaGetSymbolAddress((void**)&w2a, g_w2a);
    cudaGetSymbolAddress((void**)&w2b, g_w2b);
    cudaGetSymbolAddress((void**)&w2c, g_w2c);

    cudaFuncSetAttribute(mma_gemm<EPI_SCORE>,
                         cudaFuncAttributeMaxDynamicSharedMemorySize, MM_SMEM);
    cudaFuncSetAttribute(mma_gemm<EPI_GELU>,
                         cudaFuncAttributeMaxDynamicSharedMemorySize, MM_SMEM);
    cudaFuncSetAttribute(mma_gemm<EPI_BIAS>,
                         cudaFuncAttributeMaxDynamicSharedMemorySize, MM_SMEM);

    dim3 blk(256);
    dim3 tblk(32, 8);
    dim3 tgrid(DD / 32, DD / 32);
    dim3 grid_mlp(DD / 128, NT / 128);   // (8, 64)
    dim3 grid_big(NT / 128, NT / 128);   // (64, 64)
    unsigned nsplit = (unsigned)((size_t)NT * DD / 4 / 256);

    // weight transpose + split (once)
    tsplit<<<tgrid, tblk>>>(W1, w1a, w1b, w1c);
    tsplit<<<tgrid, tblk>>>(W2, w2a, w2b, w2c);

    // ---- projection of emb_a ----
    split3<<<nsplit, blk>>>(emb_a, e1, e2, e3);
    mma_gemm<EPI_GELU><<<grid_mlp, blk, MM_SMEM>>>(
        e1, e2, e3, w1a, w1b, w1c, b1, nullptr, t1, t2, t3, DD);
    mma_gemm<EPI_BIAS><<<grid_mlp, blk, MM_SMEM>>>(
        t1, t2, t3, w2a, w2b, w2c, b2, nullptr, a1, a2, a3, DD);

    // ---- projection of emb_b ----
    split3<<<nsplit, blk>>>(emb_b, e1, e2, e3);
    mma_gemm<EPI_GELU><<<grid_mlp, blk, MM_SMEM>>>(
        e1, e2, e3, w1a, w1b, w1c, b1, nullptr, t1, t2, t3, DD);
    mma_gemm<EPI_BIAS><<<grid_mlp, blk, MM_SMEM>>>(
        t1, t2, t3, w2a, w2b, w2c, b2, nullptr, bb1, bb2, bb3, DD);

    // ---- scores = (a @ b^T) * 20 ----
    mma_gemm<EPI_SCORE><<<grid_big, blk, MM_SMEM>>>(
        a1, a2, a3, bb1, bb2, bb3, nullptr, out, nullptr, nullptr, nullptr, NT);

    // ---- Sinkhorn iteration 1 (exact, overflow-safe) ----
    zero_vec<<<NT / 256, blk>>>(cz);
    row_lse_kernel<<<NT, blk>>>(out, cz, r);
    col_lse_partial_kernel<<<dim3((NT / 4) / 256, CSPLIT), blk>>>(out, r, p2);
    col_lse_combine_kernel<<<NT / 256, blk>>>(p2, c);

    // ---- iterations 2..20: fused fast path ----
    for (int it = 0; it < 19; it++) {
        sink_fast<<<CH, blk>>>(out, r, c, p);
        comb_add<<<NT / 256, blk>>>(p, c);
    }

    final_exp_kernel<<<(unsigned)((size_t)NT * NT / 4 / 256), blk>>>(out, r, c);
}

// round 7
// speedup vs baseline: 3.5292x; 1.0638x over previous
#include <cuda_runtime.h>
#include <cuda_fp16.h>
#include <math.h>
#include <stdint.h>

#define NT 8192
#define DD 1024
#define CSPLIT 128        // iter-1 column-partial chunks
#define CH 512            // fast-iter row chunks
#define RPC (NT / CH)     // 16 rows per chunk

typedef __half fp16;

// ---------------- scratch (device globals) ----------------
__device__ fp16 g_e1[(size_t)NT * DD], g_e2[(size_t)NT * DD];
__device__ fp16 g_t1[(size_t)NT * DD], g_t2[(size_t)NT * DD];
__device__ fp16 g_a1[(size_t)NT * DD], g_a2[(size_t)NT * DD];
__device__ fp16 g_b1[(size_t)NT * DD], g_b2[(size_t)NT * DD];
__device__ fp16 g_w1a[(size_t)DD * DD], g_w1b[(size_t)DD * DD];
__device__ fp16 g_w2a[(size_t)DD * DD], g_w2b[(size_t)DD * DD];
__device__ float  g_r[NT];
__device__ float  g_c[NT];
__device__ float  g_cz[NT];
__device__ float  g_p[(size_t)CH * NT];
__device__ float2 g_p2[(size_t)CSPLIT * NT];

// ---------------- small helpers ----------------
__device__ __forceinline__ uint32_t smem_u32(const void* p) {
    uint32_t a;
    asm("{ .reg .u64 t; cvta.to.shared.u64 t, %1; cvt.u32.u64 %0, t; }"
        : "=r"(a) : "l"(p));
    return a;
}
__device__ __forceinline__ void cp16(uint32_t dst, const void* src) {
    asm volatile("cp.async.ca.shared.global [%0], [%1], 16;"
                 :: "r"(dst), "l"(src) : "memory");
}
__device__ __forceinline__ void cp_commit() {
    asm volatile("cp.async.commit_group;" ::: "memory");
}
template <int N>
__device__ __forceinline__ void cp_wait() {
    asm volatile("cp.async.wait_group %0;" :: "n"(N) : "memory");
}
__device__ __forceinline__ void ldsm4(uint32_t& r0, uint32_t& r1,
                                      uint32_t& r2, uint32_t& r3, uint32_t a) {
    asm volatile("ldmatrix.sync.aligned.m8n8.x4.shared.b16 {%0,%1,%2,%3}, [%4];"
                 : "=r"(r0), "=r"(r1), "=r"(r2), "=r"(r3) : "r"(a));
}
__device__ __forceinline__ void mma16816(float* d, const uint32_t* a,
                                         const uint32_t* b) {
    asm volatile(
        "mma.sync.aligned.m16n8k16.row.col.f32.f16.f16.f32 "
        "{%0,%1,%2,%3}, {%4,%5,%6,%7}, {%8,%9}, {%0,%1,%2,%3};"
        : "+f"(d[0]), "+f"(d[1]), "+f"(d[2]), "+f"(d[3])
        : "r"(a[0]), "r"(a[1]), "r"(a[2]), "r"(a[3]), "r"(b[0]), "r"(b[1]));
}

__device__ __forceinline__ void split1(float v, fp16& h1, fp16& h2)
{
    h1 = __float2half_rn(v);
    h2 = __float2half_rn(v - __half2float(h1));
}

// ================= fp16x2 split of a full fp32 array =================
__global__ void __launch_bounds__(256)
split2(const float* __restrict__ x, fp16* __restrict__ o1,
       fp16* __restrict__ o2)
{
    size_t i4 = (size_t)blockIdx.x * 256 + threadIdx.x;
    float4 v = ((const float4*)x)[i4];
    float vv[4] = {v.x, v.y, v.z, v.w};
    fp16 e1[4], e2[4];
#pragma unroll
    for (int k = 0; k < 4; k++) split1(vv[k], e1[k], e2[k]);
    ((uint2*)o1)[i4] = *(uint2*)e1;
    ((uint2*)o2)[i4] = *(uint2*)e2;
}

// ================= transpose + split W [K,N] -> Wt splits [N,K] ============
__global__ void __launch_bounds__(256)
tsplit(const float* __restrict__ W, fp16* __restrict__ o1,
       fp16* __restrict__ o2)
{
    __shared__ float tile[32][33];
    const int bn = blockIdx.x * 32;
    const int bk = blockIdx.y * 32;
    const int tx = threadIdx.x, ty = threadIdx.y;   // 32 x 8
#pragma unroll
    for (int i = 0; i < 32; i += 8)
        tile[ty + i][tx] = W[(size_t)(bk + ty + i) * DD + bn + tx];
    __syncthreads();
#pragma unroll
    for (int i = 0; i < 32; i += 8) {
        float v = tile[tx][ty + i];
        fp16 h1, h2;
        split1(v, h1, h2);
        size_t off = (size_t)(bn + ty + i) * DD + bk + tx;
        o1[off] = h1; o2[off] = h2;
    }
}

// ================= mma.sync fp16x3-pair GEMM: acc = A · B^T ================
// Tile 128x128, BK=64, 4 split tiles resident per k-chunk, double-buffered.
#define BKC 64
#define AST 72                  // padded smem stride (fp16)
#define TSZ (128 * AST)         // fp16 per tile
#define NCHK (DD / BKC)         // 16
#define MM_SMEM (2 * 4 * TSZ * 2)  // 147456 bytes

enum { EPI_SCORE = 0, EPI_GELU = 1, EPI_BIAS = 2 };

template <int EPI>
__global__ void __launch_bounds__(256, 1)
mma_gemm(const fp16* __restrict__ A1, const fp16* __restrict__ A2,
         const fp16* __restrict__ B1, const fp16* __restrict__ B2,
         const float* __restrict__ bias, float* __restrict__ Cf,
         fp16* __restrict__ O1, fp16* __restrict__ O2, int ldc)
{
    extern __shared__ __align__(16) fp16 sm[];
    const uint32_t sS = smem_u32(sm);
    const int tid = threadIdx.x;
    const int wid = tid >> 5, lane = tid & 31;
    const int bm = blockIdx.y * 128, bn = blockIdx.x * 128;
    const int wm = (wid & 1) * 64, wn = (wid >> 1) * 32;

    const fp16* tsrc[4] = {
        A1 + (size_t)bm * DD, A2 + (size_t)bm * DD,
        B1 + (size_t)bn * DD, B2 + (size_t)bn * DD};

    // term pairs: (A1,B1), (A1,B2), (A2,B1)
    const int pa[3] = {0, 0, 1};
    const int pb[3] = {0, 1, 0};

    float acc[4][4][4];
#pragma unroll
    for (int i = 0; i < 4; i++)
#pragma unroll
        for (int j = 0; j < 4; j++)
#pragma unroll
            for (int k = 0; k < 4; k++) acc[i][j][k] = 0.0f;

    const int lrow = tid >> 3;         // 0..31
    const int lseg = (tid & 7) * 8;    // fp16 offset 0..56

#pragma unroll
    for (int t = 0; t < 4; t++) {
#pragma unroll
        for (int p = 0; p < 4; p++) {
            int row = lrow + p * 32;
            cp16(sS + (uint32_t)(t * TSZ + row * AST + lseg) * 2,
                 tsrc[t] + (size_t)row * DD + lseg);
        }
    }
    cp_commit();

    int buf = 0;
    for (int ch = 0; ch < NCHK; ch++) {
        if (ch + 1 < NCHK) {
            const int k0 = (ch + 1) * BKC;
            const int bo = (buf ^ 1) * 4 * TSZ;
#pragma unroll
            for (int t = 0; t < 4; t++) {
#pragma unroll
                for (int p = 0; p < 4; p++) {
                    int row = lrow + p * 32;
                    cp16(sS + (uint32_t)(bo + t * TSZ + row * AST + lseg) * 2,
                         tsrc[t] + (size_t)row * DD + k0 + lseg);
                }
            }
            cp_commit();
            cp_wait<1>();
        } else {
            cp_wait<0>();
        }
        __syncthreads();

        const int bo = buf * 4 * TSZ;
#pragma unroll
        for (int pr = 0; pr < 3; pr++) {
            const uint32_t baseA = sS + (uint32_t)(bo + pa[pr] * TSZ) * 2;
            const uint32_t baseB = sS + (uint32_t)(bo + (2 + pb[pr]) * TSZ) * 2;
#pragma unroll
            for (int kt = 0; kt < 4; kt++) {
                uint32_t af[4][4];
#pragma unroll
                for (int mt = 0; mt < 4; mt++) {
                    uint32_t addr = baseA +
                        (uint32_t)((wm + mt * 16 + (lane & 15)) * AST +
                                   kt * 16 + (lane >> 4) * 8) * 2;
                    ldsm4(af[mt][0], af[mt][1], af[mt][2], af[mt][3], addr);
                }
                uint32_t bfr[2][4];
#pragma unroll
                for (int np = 0; np < 2; np++) {
                    uint32_t addr = baseB +
                        (uint32_t)((wn + np * 16 + (lane & 7) +
                                    ((lane >> 4) << 3)) * AST +
                                   kt * 16 + ((lane >> 3) & 1) * 8) * 2;
                    ldsm4(bfr[np][0], bfr[np][1], bfr[np][2], bfr[np][3], addr);
                }
#pragma unroll
                for (int mt = 0; mt < 4; mt++)
#pragma unroll
                    for (int nt = 0; nt < 4; nt++) {
                        uint32_t bb[2] = {bfr[nt >> 1][(nt & 1) * 2],
                                          bfr[nt >> 1][(nt & 1) * 2 + 1]};
                        mma16816(acc[mt][nt], af[mt], bb);
                    }
            }
        }
        __syncthreads();
        buf ^= 1;
    }

    // epilogue
#pragma unroll
    for (int mt = 0; mt < 4; mt++) {
#pragma unroll
        for (int nt = 0; nt < 4; nt++) {
            int row = bm + wm + mt * 16 + (lane >> 2);
            int col = bn + wn + nt * 8 + (lane & 3) * 2;
            float* d = acc[mt][nt];
            if (EPI == EPI_SCORE) {
                *(float2*)&Cf[(size_t)row * ldc + col] =
                    make_float2(d[0] * 20.0f, d[1] * 20.0f);
                *(float2*)&Cf[(size_t)(row + 8) * ldc + col] =
                    make_float2(d[2] * 20.0f, d[3] * 20.0f);
            } else {
                float bx = bias[col], by = bias[col + 1];
                float v[4] = {d[0] + bx, d[1] + by, d[2] + bx, d[3] + by};
                if (EPI == EPI_GELU) {
#pragma unroll
                    for (int k = 0; k < 4; k++)
                        v[k] = 0.5f * v[k] *
                               (1.0f + erff(v[k] * 0.70710678118654752f));
                }
#pragma unroll
                for (int h = 0; h < 2; h++) {
                    fp16 s1[2], s2[2];
                    split1(v[2 * h + 0], s1[0], s2[0]);
                    split1(v[2 * h + 1], s1[1], s2[1]);
                    size_t off = (size_t)(row + 8 * h) * ldc + col;
                    *(uint32_t*)(O1 + off) = *(uint32_t*)s1;
                    *(uint32_t*)(O2 + off) = *(uint32_t*)s2;
                }
            }
        }
    }
}

// ================= Sinkhorn (R5/R6-proven) =================
__device__ __forceinline__ void lse_upd(float& m, float& l, float v)
{
    if (v <= m) {
        l += __expf(v - m);
    } else {
        l = fmaf(l, __expf(m - v), 1.0f);
        m = v;
    }
}

__global__ void zero_vec(float* __restrict__ c)
{
    c[blockIdx.x * 256 + threadIdx.x] = 0.0f;
}

__global__ void __launch_bounds__(256)
row_lse_kernel(const float* __restrict__ S, const float* __restrict__ c,
               float* __restrict__ r)
{
    const int row = blockIdx.x;
    const int tid = threadIdx.x;
    const float4* s4 = (const float4*)(S + (size_t)row * NT);
    const float4* c4 = (const float4*)c;

    float m = -INFINITY, l = 0.0f;
    for (int j = tid; j < NT / 4; j += 256) {
        float4 s = s4[j];
        float4 cc = c4[j];
        lse_upd(m, l, s.x - cc.x);
        lse_upd(m, l, s.y - cc.y);
        lse_upd(m, l, s.z - cc.z);
        lse_upd(m, l, s.w - cc.w);
    }

    __shared__ float sm[256], sl[256];
    sm[tid] = m; sl[tid] = l;
    __syncthreads();
    for (int s = 128; s > 0; s >>= 1) {
        if (tid < s) {
            float m2 = sm[tid + s], l2 = sl[tid + s];
            float nm = fmaxf(sm[tid], m2);
            sl[tid] = sl[tid] * __expf(sm[tid] - nm) + l2 * __expf(m2 - nm);
            sm[tid] = nm;
        }
        __syncthreads();
    }
    if (tid == 0) r[row] = sm[0] + __logf(sl[0]);
}

__global__ void __launch_bounds__(256)
col_lse_partial_kernel(const float* __restrict__ S, const float* __restrict__ r,
                       float2* __restrict__ part)
{
    const int j4 = blockIdx.x * blockDim.x + threadIdx.x;
    const int chunk = blockIdx.y;
    const int rowsPer = NT / CSPLIT;
    const int i0 = chunk * rowsPer;

    float m0 = -INFINITY, m1 = -INFINITY, m2 = -INFINITY, m3 = -INFINITY;
    float l0 = 0.f, l1 = 0.f, l2 = 0.f, l3 = 0.f;

    const float4* S4 = (const float4*)S;
    for (int i = i0; i < i0 + rowsPer; i++) {
        float4 s = S4[(size_t)i * (NT / 4) + j4];
        float rv = __ldg(&r[i]);
        lse_upd(m0, l0, s.x - rv);
        lse_upd(m1, l1, s.y - rv);
        lse_upd(m2, l2, s.z - rv);
        lse_upd(m3, l3, s.w - rv);
    }
    int j = j4 * 4;
    float2* p = part + (size_t)chunk * NT + j;
    p[0] = make_float2(m0, l0);
    p[1] = make_float2(m1, l1);
    p[2] = make_float2(m2, l2);
    p[3] = make_float2(m3, l3);
}

__global__ void __launch_bounds__(256)
col_lse_combine_kernel(const float2* __restrict__ part, float* __restrict__ c)
{
    const int j = blockIdx.x * blockDim.x + threadIdx.x;
    float m = -INFINITY, l = 0.0f;
    for (int k = 0; k < CSPLIT; k++) {
        float2 p = part[(size_t)k * NT + j];
        float nm = fmaxf(m, p.x);
        l = l * __expf(m - nm) + p.y * __expf(p.x - nm);
        m = nm;
    }
    c[j] = m + __logf(l);
}

__device__ __forceinline__ float blk_sum(float x, float* sb, int tid)
{
#pragma unroll
    for (int o = 16; o; o >>= 1) x += __shfl_down_sync(0xffffffffu, x, o);
    if ((tid & 31) == 0) sb[tid >> 5] = x;
    __syncthreads();
    if (tid < 32) {
        float y = (tid < 8) ? sb[tid] : 0.0f;
#pragma unroll
        for (int o = 4; o; o >>= 1) y += __shfl_down_sync(0xffffffffu, y, o);
        if (tid == 0) sb[32] = y;
    }
    __syncthreads();
    float r = sb[32];
    __syncthreads();
    return r;
}

__global__ void __launch_bounds__(256)
sink_fast(const float* __restrict__ S, float* __restrict__ r,
          const float* __restrict__ c, float* __restrict__ part)
{
    __shared__ float cc[NT];
    __shared__ float sb[40];
    const int tid = threadIdx.x, chunk = blockIdx.x;

    for (int k = tid; k < NT / 4; k += 256)
        ((float4*)cc)[k] = ((const float4*)c)[k];
    __syncthreads();

    float acc[32];
#pragma unroll
    for (int k = 0; k < 32; k++) acc[k] = 0.0f;

    for (int i = chunk * RPC; i < chunk * RPC + RPC; i++) {
        const float4* S4 = (const float4*)(S + (size_t)i * NT);
        const float rr = r[i];
        float4 e[8];
        float dot = 0.0f;
#pragma unroll
        for (int q = 0; q < 8; q++) {
            float4 s = S4[tid + 256 * q];
            float4 cv = *(const float4*)&cc[4 * (tid + 256 * q)];
            e[q].x = __expf(s.x - cv.x - rr);
            e[q].y = __expf(s.y - cv.y - rr);
            e[q].z = __expf(s.z - cv.z - rr);
            e[q].w = __expf(s.w - cv.w - rr);
            dot += (e[q].x + e[q].y) + (e[q].z + e[q].w);
        }
        dot = blk_sum(dot, sb, tid);
        float w = __fdividef(1.0f, dot);
        if (tid == 0) r[i] = rr + __logf(dot);
#pragma unroll
        for (int q = 0; q < 8; q++) {
            acc[4 * q + 0] = fmaf(e[q].x, w, acc[4 * q + 0]);
            acc[4 * q + 1] = fmaf(e[q].y, w, acc[4 * q + 1]);
            acc[4 * q + 2] = fmaf(e[q].z, w, acc[4 * q + 2]);
            acc[4 * q + 3] = fmaf(e[q].w, w, acc[4 * q + 3]);
        }
    }
    float* pp = part + (size_t)chunk * NT;
#pragma unroll
    for (int q = 0; q < 8; q++) {
        int j = 4 * (tid + 256 * q);
        *(float4*)&pp[j] = make_float4(acc[4 * q + 0], acc[4 * q + 1],
                                       acc[4 * q + 2], acc[4 * q + 3]);
    }
}

__global__ void __launch_bounds__(256)
comb_add(const float* __restrict__ part, float* __restrict__ c)
{
    const int j = blockIdx.x * 256 + threadIdx.x;
    float s = 0.0f;
    for (int k = 0; k < CH; k++) s += part[(size_t)k * NT + j];
    c[j] += __logf(s);
}

__global__ void __launch_bounds__(256)
final_exp_kernel(float* __restrict__ S, const float* __restrict__ r,
                 const float* __restrict__ c)
{
    size_t idx = (size_t)blockIdx.x * blockDim.x + threadIdx.x;
    int row = (int)(idx >> 11);
    int j4 = (int)(idx & 2047);
    float4 s = ((const float4*)S)[idx];
    float rv = r[row];
    float4 cc = ((const float4*)c)[j4];
    s.x = __expf(s.x - rv - cc.x);
    s.y = __expf(s.y - rv - cc.y);
    s.z = __expf(s.z - rv - cc.z);
    s.w = __expf(s.w - rv - cc.w);
    ((float4*)S)[idx] = s;
}

// ---------------- launch ----------------
extern "C" void kernel_launch(void* const* d_in, const int* in_sizes, int n_in,
                              void* d_out, int out_size)
{
    const float* emb_a = (const float*)d_in[0];
    const float* emb_b = (const float*)d_in[1];
    const float* W1    = (const float*)d_in[2];
    const float* b1    = (const float*)d_in[3];
    const float* W2    = (const float*)d_in[4];
    const float* b2    = (const float*)d_in[5];
    float* out = (float*)d_out;

    float *r, *c, *cz, *p;
    float2* p2;
    fp16 *e1, *e2, *t1, *t2, *a1, *a2, *bb1, *bb2;
    fp16 *w1a, *w1b, *w2a, *w2b;
    cudaGetSymbolAddress((void**)&r, g_r);
    cudaGetSymbolAddress((void**)&c, g_c);
    cudaGetSymbolAddress((void**)&cz, g_cz);
    cudaGetSymbolAddress((void**)&p, g_p);
    cudaGetSymbolAddress((void**)&p2, g_p2);
    cudaGetSymbolAddress((void**)&e1, g_e1);
    cudaGetSymbolAddress((void**)&e2, g_e2);
    cudaGetSymbolAddress((void**)&t1, g_t1);
    cudaGetSymbolAddress((void**)&t2, g_t2);
    cudaGetSymbolAddress((void**)&a1, g_a1);
    cudaGetSymbolAddress((void**)&a2, g_a2);
    cudaGetSymbolAddress((void**)&bb1, g_b1);
    cudaGetSymbolAddress((void**)&bb2, g_b2);
    cudaGetSymbolAddress((void**)&w1a, g_w1a);
    cudaGetSymbolAddress((void**)&w1b, g_w1b);
    cudaGetSymbolAddress((void**)&w2a, g_w2a);
    cudaGetSymbolAddress((void**)&w2b, g_w2b);

    cudaFuncSetAttribute(mma_gemm<EPI_SCORE>,
                         cudaFuncAttributeMaxDynamicSharedMemorySize, MM_SMEM);
    cudaFuncSetAttribute(mma_gemm<EPI_GELU>,
                         cudaFuncAttributeMaxDynamicSharedMemorySize, MM_SMEM);
    cudaFuncSetAttribute(mma_gemm<EPI_BIAS>,
                         cudaFuncAttributeMaxDynamicSharedMemorySize, MM_SMEM);

    dim3 blk(256);
    dim3 tblk(32, 8);
    dim3 tgrid(DD / 32, DD / 32);
    dim3 grid_mlp(DD / 128, NT / 128);   // (8, 64)
    dim3 grid_big(NT / 128, NT / 128);   // (64, 64)
    unsigned nsplit = (unsigned)((size_t)NT * DD / 4 / 256);

    // weight transpose + split (once)
    tsplit<<<tgrid, tblk>>>(W1, w1a, w1b);
    tsplit<<<tgrid, tblk>>>(W2, w2a, w2b);

    // ---- projection of emb_a ----
    split2<<<nsplit, blk>>>(emb_a, e1, e2);
    mma_gemm<EPI_GELU><<<grid_mlp, blk, MM_SMEM>>>(
        e1, e2, w1a, w1b, b1, nullptr, t1, t2, DD);
    mma_gemm<EPI_BIAS><<<grid_mlp, blk, MM_SMEM>>>(
        t1, t2, w2a, w2b, b2, nullptr, a1, a2, DD);

    // ---- projection of emb_b ----
    split2<<<nsplit, blk>>>(emb_b, e1, e2);
    mma_gemm<EPI_GELU><<<grid_mlp, blk, MM_SMEM>>>(
        e1, e2, w1a, w1b, b1, nullptr, t1, t2, DD);
    mma_gemm<EPI_BIAS><<<grid_mlp, blk, MM_SMEM>>>(
        t1, t2, w2a, w2b, b2, nullptr, bb1, bb2, DD);

    // ---- scores = (a @ b^T) * 20 ----
    mma_gemm<EPI_SCORE><<<grid_big, blk, MM_SMEM>>>(
        a1, a2, bb1, bb2, nullptr, out, nullptr, nullptr, NT);

    // ---- Sinkhorn iteration 1 (exact, overflow-safe) ----
    zero_vec<<<NT / 256, blk>>>(cz);
    row_lse_kernel<<<NT, blk>>>(out, cz, r);
    col_lse_partial_kernel<<<dim3((NT / 4) / 256, CSPLIT), blk>>>(out, r, p2);
    col_lse_combine_kernel<<<NT / 256, blk>>>(p2, c);

    // ---- iterations 2..20: fused fast path ----
    for (int it = 0; it < 19; it++) {
        sink_fast<<<CH, blk>>>(out, r, c, p);
        comb_add<<<NT / 256, blk>>>(p, c);
    }

    final_exp_kernel<<<(unsigned)((size_t)NT * NT / 4 / 256), blk>>>(out, r, c);
}

// round 8
// speedup vs baseline: 4.7002x; 1.3318x over previous
#include <cuda_runtime.h>
#include <cuda_fp16.h>
#include <math.h>
#include <stdint.h>

#define NT 8192
#define DD 1024
#define CSPLIT 128        // iter-1 column-partial chunks
#define CH 512            // fast-iter row chunks
#define RPC (NT / CH)     // 16 rows per chunk

typedef __half fp16;

// ---------------- scratch (device globals) ----------------
__device__ fp16 g_e1[(size_t)NT * DD], g_e2[(size_t)NT * DD];
__device__ fp16 g_t1[(size_t)NT * DD], g_t2[(size_t)NT * DD];
__device__ fp16 g_a1[(size_t)NT * DD], g_a2[(size_t)NT * DD];
__device__ fp16 g_b1[(size_t)NT * DD], g_b2[(size_t)NT * DD];
__device__ fp16 g_w1a[(size_t)DD * DD], g_w1b[(size_t)DD * DD];
__device__ fp16 g_w2a[(size_t)DD * DD], g_w2b[(size_t)DD * DD];
__device__ float  g_r[NT];
__device__ float  g_c[NT];
__device__ float  g_cz[NT];
__device__ float  g_p[(size_t)CH * NT];
__device__ float2 g_p2[(size_t)CSPLIT * NT];

// ---------------- small helpers ----------------
__device__ __forceinline__ uint32_t smem_u32(const void* p) {
    uint32_t a;
    asm("{ .reg .u64 t; cvta.to.shared.u64 t, %1; cvt.u32.u64 %0, t; }"
        : "=r"(a) : "l"(p));
    return a;
}
__device__ __forceinline__ void cp16(uint32_t dst, const void* src) {
    asm volatile("cp.async.ca.shared.global [%0], [%1], 16;"
                 :: "r"(dst), "l"(src) : "memory");
}
__device__ __forceinline__ void cp_commit() {
    asm volatile("cp.async.commit_group;" ::: "memory");
}
template <int N>
__device__ __forceinline__ void cp_wait() {
    asm volatile("cp.async.wait_group %0;" :: "n"(N) : "memory");
}
__device__ __forceinline__ void ldsm4(uint32_t& r0, uint32_t& r1,
                                      uint32_t& r2, uint32_t& r3, uint32_t a) {
    asm volatile("ldmatrix.sync.aligned.m8n8.x4.shared.b16 {%0,%1,%2,%3}, [%4];"
                 : "=r"(r0), "=r"(r1), "=r"(r2), "=r"(r3) : "r"(a));
}
__device__ __forceinline__ void mma16816(float* d, const uint32_t* a,
                                         const uint32_t* b) {
    asm volatile(
        "mma.sync.aligned.m16n8k16.row.col.f32.f16.f16.f32 "
        "{%0,%1,%2,%3}, {%4,%5,%6,%7}, {%8,%9}, {%0,%1,%2,%3};"
        : "+f"(d[0]), "+f"(d[1]), "+f"(d[2]), "+f"(d[3])
        : "r"(a[0]), "r"(a[1]), "r"(a[2]), "r"(a[3]), "r"(b[0]), "r"(b[1]));
}

__device__ __forceinline__ void split1(float v, fp16& h1, fp16& h2)
{
    h1 = __float2half_rn(v);
    h2 = __float2half_rn(v - __half2float(h1));
}

// ================= fp16x2 split of a full fp32 array =================
__global__ void __launch_bounds__(256)
split2(const float* __restrict__ x, fp16* __restrict__ o1,
       fp16* __restrict__ o2)
{
    size_t i4 = (size_t)blockIdx.x * 256 + threadIdx.x;
    float4 v = ((const float4*)x)[i4];
    float vv[4] = {v.x, v.y, v.z, v.w};
    fp16 e1[4], e2[4];
#pragma unroll
    for (int k = 0; k < 4; k++) split1(vv[k], e1[k], e2[k]);
    ((uint2*)o1)[i4] = *(uint2*)e1;
    ((uint2*)o2)[i4] = *(uint2*)e2;
}

// ================= transpose + split W [K,N] -> Wt splits [N,K] ============
__global__ void __launch_bounds__(256)
tsplit(const float* __restrict__ W, fp16* __restrict__ o1,
       fp16* __restrict__ o2)
{
    __shared__ float tile[32][33];
    const int bn = blockIdx.x * 32;
    const int bk = blockIdx.y * 32;
    const int tx = threadIdx.x, ty = threadIdx.y;   // 32 x 8
#pragma unroll
    for (int i = 0; i < 32; i += 8)
        tile[ty + i][tx] = W[(size_t)(bk + ty + i) * DD + bn + tx];
    __syncthreads();
#pragma unroll
    for (int i = 0; i < 32; i += 8) {
        float v = tile[tx][ty + i];
        fp16 h1, h2;
        split1(v, h1, h2);
        size_t off = (size_t)(bn + ty + i) * DD + bk + tx;
        o1[off] = h1; o2[off] = h2;
    }
}

// ================= mma.sync fp16x3-pair GEMM: acc = A · B^T ================
// Tile 128x128, BK=64, 4 split tiles per stage, 3-stage cp.async pipeline.
#define BKC 64
#define AST 72                  // padded smem stride (fp16)
#define TSZ (128 * AST)         // fp16 per tile
#define NCHK (DD / BKC)         // 16
#define NSTG 3
#define MM_SMEM (NSTG * 4 * TSZ * 2)  // 221184 bytes

enum { EPI_SCORE = 0, EPI_GELU = 1, EPI_BIAS = 2 };

template <int EPI>
__global__ void __launch_bounds__(256, 1)
mma_gemm(const fp16* __restrict__ A1, const fp16* __restrict__ A2,
         const fp16* __restrict__ B1, const fp16* __restrict__ B2,
         const float* __restrict__ bias, float* __restrict__ Cf,
         fp16* __restrict__ O1, fp16* __restrict__ O2, int ldc)
{
    extern __shared__ __align__(16) fp16 sm[];
    const uint32_t sS = smem_u32(sm);
    const int tid = threadIdx.x;
    const int wid = tid >> 5, lane = tid & 31;
    const int bm = blockIdx.y * 128, bn = blockIdx.x * 128;
    const int wm = (wid & 1) * 64, wn = (wid >> 1) * 32;

    const fp16* tsrc[4] = {
        A1 + (size_t)bm * DD, A2 + (size_t)bm * DD,
        B1 + (size_t)bn * DD, B2 + (size_t)bn * DD};

    float acc[4][4][4];
#pragma unroll
    for (int i = 0; i < 4; i++)
#pragma unroll
        for (int j = 0; j < 4; j++)
#pragma unroll
            for (int k = 0; k < 4; k++) acc[i][j][k] = 0.0f;

    const int lrow = tid >> 3;         // 0..31
    const int lseg = (tid & 7) * 8;    // fp16 offset 0..56

    // loader for one chunk into a stage
    auto load_chunk = [&](int stage, int k0) {
        const uint32_t so = (uint32_t)(stage * 4 * TSZ);
#pragma unroll
        for (int t = 0; t < 4; t++) {
#pragma unroll
            for (int p = 0; p < 4; p++) {
                int row = lrow + p * 32;
                cp16(sS + (so + (uint32_t)(t * TSZ + row * AST + lseg)) * 2,
                     tsrc[t] + (size_t)row * DD + k0 + lseg);
            }
        }
    };

    // prefetch chunks 0,1
    load_chunk(0, 0);
    cp_commit();
    load_chunk(1, BKC);
    cp_commit();

    for (int ch = 0; ch < NCHK; ch++) {
        // chunk ch must be complete; only chunk ch+1 may remain in flight
        if (ch < NCHK - 1) cp_wait<1>(); else cp_wait<0>();
        __syncthreads();
        // prefetch ch+2 into the stage freed by ch-1 (all warps passed it)
        if (ch + 2 < NCHK) {
            load_chunk((ch + 2) % NSTG, (ch + 2) * BKC);
            cp_commit();
        }

        const uint32_t bo = (uint32_t)((ch % NSTG) * 4 * TSZ);
#pragma unroll
        for (int kt = 0; kt < 4; kt++) {
            // A fragments for both splits (A1 reused by 2 products)
            uint32_t afA[2][4][4];
#pragma unroll
            for (int s = 0; s < 2; s++)
#pragma unroll
                for (int mt = 0; mt < 4; mt++) {
                    uint32_t addr = sS +
                        (bo + (uint32_t)(s * TSZ +
                            (wm + mt * 16 + (lane & 15)) * AST +
                            kt * 16 + (lane >> 4) * 8)) * 2;
                    ldsm4(afA[s][mt][0], afA[s][mt][1],
                          afA[s][mt][2], afA[s][mt][3], addr);
                }
            // B fragments for both splits (B1 reused by 2 products)
            uint32_t bfr[2][2][4];
#pragma unroll
            for (int s = 0; s < 2; s++)
#pragma unroll
                for (int np = 0; np < 2; np++) {
                    uint32_t addr = sS +
                        (bo + (uint32_t)((2 + s) * TSZ +
                            (wn + np * 16 + (lane & 7) +
                             ((lane >> 4) << 3)) * AST +
                            kt * 16 + ((lane >> 3) & 1) * 8)) * 2;
                    ldsm4(bfr[s][np][0], bfr[s][np][1],
                          bfr[s][np][2], bfr[s][np][3], addr);
                }
            // products: A1*B1 + A1*B2 + A2*B1
#pragma unroll
            for (int mt = 0; mt < 4; mt++)
#pragma unroll
                for (int nt = 0; nt < 4; nt++) {
                    uint32_t b1v[2] = {bfr[0][nt >> 1][(nt & 1) * 2],
                                       bfr[0][nt >> 1][(nt & 1) * 2 + 1]};
                    uint32_t b2v[2] = {bfr[1][nt >> 1][(nt & 1) * 2],
                                       bfr[1][nt >> 1][(nt & 1) * 2 + 1]};
                    mma16816(acc[mt][nt], afA[0][mt], b1v);
                    mma16816(acc[mt][nt], afA[0][mt], b2v);
                    mma16816(acc[mt][nt], afA[1][mt], b1v);
                }
        }
    }

    // epilogue
#pragma unroll
    for (int mt = 0; mt < 4; mt++) {
#pragma unroll
        for (int nt = 0; nt < 4; nt++) {
            int row = bm + wm + mt * 16 + (lane >> 2);
            int col = bn + wn + nt * 8 + (lane & 3) * 2;
            float* d = acc[mt][nt];
            if (EPI == EPI_SCORE) {
                *(float2*)&Cf[(size_t)row * ldc + col] =
                    make_float2(d[0] * 20.0f, d[1] * 20.0f);
                *(float2*)&Cf[(size_t)(row + 8) * ldc + col] =
                    make_float2(d[2] * 20.0f, d[3] * 20.0f);
            } else {
                float bx = bias[col], by = bias[col + 1];
                float v[4] = {d[0] + bx, d[1] + by, d[2] + bx, d[3] + by};
                if (EPI == EPI_GELU) {
#pragma unroll
                    for (int k = 0; k < 4; k++)
                        v[k] = 0.5f * v[k] *
                               (1.0f + erff(v[k] * 0.70710678118654752f));
                }
#pragma unroll
                for (int h = 0; h < 2; h++) {
                    fp16 s1[2], s2[2];
                    split1(v[2 * h + 0], s1[0], s2[0]);
                    split1(v[2 * h + 1], s1[1], s2[1]);
                    size_t off = (size_t)(row + 8 * h) * ldc + col;
                    *(uint32_t*)(O1 + off) = *(uint32_t*)s1;
                    *(uint32_t*)(O2 + off) = *(uint32_t*)s2;
                }
            }
        }
    }
}

// ================= Sinkhorn (R5/R6-proven) =================
__device__ __forceinline__ void lse_upd(float& m, float& l, float v)
{
    if (v <= m) {
        l += __expf(v - m);
    } else {
        l = fmaf(l, __expf(m - v), 1.0f);
        m = v;
    }
}

__global__ void zero_vec(float* __restrict__ c)
{
    c[blockIdx.x * 256 + threadIdx.x] = 0.0f;
}

__global__ void __launch_bounds__(256)
row_lse_kernel(const float* __restrict__ S, const float* __restrict__ c,
               float* __restrict__ r)
{
    const int row = blockIdx.x;
    const int tid = threadIdx.x;
    const float4* s4 = (const float4*)(S + (size_t)row * NT);
    const float4* c4 = (const float4*)c;

    float m = -INFINITY, l = 0.0f;
    for (int j = tid; j < NT / 4; j += 256) {
        float4 s = s4[j];
        float4 cc = c4[j];
        lse_upd(m, l, s.x - cc.x);
        lse_upd(m, l, s.y - cc.y);
        lse_upd(m, l, s.z - cc.z);
        lse_upd(m, l, s.w - cc.w);
    }

    __shared__ float sm[256], sl[256];
    sm[tid] = m; sl[tid] = l;
    __syncthreads();
    for (int s = 128; s > 0; s >>= 1) {
        if (tid < s) {
            float m2 = sm[tid + s], l2 = sl[tid + s];
            float nm = fmaxf(sm[tid], m2);
            sl[tid] = sl[tid] * __expf(sm[tid] - nm) + l2 * __expf(m2 - nm);
            sm[tid] = nm;
        }
        __syncthreads();
    }
    if (tid == 0) r[row] = sm[0] + __logf(sl[0]);
}

__global__ void __launch_bounds__(256)
col_lse_partial_kernel(const float* __restrict__ S, const float* __restrict__ r,
                       float2* __restrict__ part)
{
    const int j4 = blockIdx.x * blockDim.x + threadIdx.x;
    const int chunk = blockIdx.y;
    const int rowsPer = NT / CSPLIT;
    const int i0 = chunk * rowsPer;

    float m0 = -INFINITY, m1 = -INFINITY, m2 = -INFINITY, m3 = -INFINITY;
    float l0 = 0.f, l1 = 0.f, l2 = 0.f, l3 = 0.f;

    const float4* S4 = (const float4*)S;
    for (int i = i0; i < i0 + rowsPer; i++) {
        float4 s = S4[(size_t)i * (NT / 4) + j4];
        float rv = __ldg(&r[i]);
        lse_upd(m0, l0, s.x - rv);
        lse_upd(m1, l1, s.y - rv);
        lse_upd(m2, l2, s.z - rv);
        lse_upd(m3, l3, s.w - rv);
    }
    int j = j4 * 4;
    float2* p = part + (size_t)chunk * NT + j;
    p[0] = make_float2(m0, l0);
    p[1] = make_float2(m1, l1);
    p[2] = make_float2(m2, l2);
    p[3] = make_float2(m3, l3);
}

__global__ void __launch_bounds__(256)
col_lse_combine_kernel(const float2* __restrict__ part, float* __restrict__ c)
{
    const int j = blockIdx.x * blockDim.x + threadIdx.x;
    float m = -INFINITY, l = 0.0f;
    for (int k = 0; k < CSPLIT; k++) {
        float2 p = part[(size_t)k * NT + j];
        float nm = fmaxf(m, p.x);
        l = l * __expf(m - nm) + p.y * __expf(p.x - nm);
        m = nm;
    }
    c[j] = m + __logf(l);
}

__device__ __forceinline__ float blk_sum(float x, float* sb, int tid)
{
#pragma unroll
    for (int o = 16; o; o >>= 1) x += __shfl_down_sync(0xffffffffu, x, o);
    if ((tid & 31) == 0) sb[tid >> 5] = x;
    __syncthreads();
    if (tid < 32) {
        float y = (tid < 8) ? sb[tid] : 0.0f;
#pragma unroll
        for (int o = 4; o; o >>= 1) y += __shfl_down_sync(0xffffffffu, y, o);
        if (tid == 0) sb[32] = y;
    }
    __syncthreads();
    float r = sb[32];
    __syncthreads();
    return r;
}

__global__ void __launch_bounds__(256)
sink_fast(const float* __restrict__ S, float* __restrict__ r,
          const float* __restrict__ c, float* __restrict__ part)
{
    __shared__ float cc[NT];
    __shared__ float sb[40];
    const int tid = threadIdx.x, chunk = blockIdx.x;

    for (int k = tid; k < NT / 4; k += 256)
        ((float4*)cc)[k] = ((const float4*)c)[k];
    __syncthreads();

    float acc[32];
#pragma unroll
    for (int k = 0; k < 32; k++) acc[k] = 0.0f;

    for (int i = chunk * RPC; i < chunk * RPC + RPC; i++) {
        const float4* S4 = (const float4*)(S + (size_t)i * NT);
        const float rr = r[i];
        float4 e[8];
        float dot = 0.0f;
#pragma unroll
        for (int q = 0; q < 8; q++) {
            float4 s = S4[tid + 256 * q];
            float4 cv = *(const float4*)&cc[4 * (tid + 256 * q)];
            e[q].x = __expf(s.x - cv.x - rr);
            e[q].y = __expf(s.y - cv.y - rr);
            e[q].z = __expf(s.z - cv.z - rr);
            e[q].w = __expf(s.w - cv.w - rr);
            dot += (e[q].x + e[q].y) + (e[q].z + e[q].w);
        }
        dot = blk_sum(dot, sb, tid);
        float w = __fdividef(1.0f, dot);
        if (tid == 0) r[i] = rr + __logf(dot);
#pragma unroll
        for (int q = 0; q < 8; q++) {
            acc[4 * q + 0] = fmaf(e[q].x, w, acc[4 * q + 0]);
            acc[4 * q + 1] = fmaf(e[q].y, w, acc[4 * q + 1]);
            acc[4 * q + 2] = fmaf(e[q].z, w, acc[4 * q + 2]);
            acc[4 * q + 3] = fmaf(e[q].w, w, acc[4 * q + 3]);
        }
    }
    float* pp = part + (size_t)chunk * NT;
#pragma unroll
    for (int q = 0; q < 8; q++) {
        int j = 4 * (tid + 256 * q);
        *(float4*)&pp[j] = make_float4(acc[4 * q + 0], acc[4 * q + 1],
                                       acc[4 * q + 2], acc[4 * q + 3]);
    }
}

__global__ void __launch_bounds__(256)
comb_add(const float* __restrict__ part, float* __restrict__ c)
{
    const int j = blockIdx.x * 256 + threadIdx.x;
    float s = 0.0f;
    for (int k = 0; k < CH; k++) s += part[(size_t)k * NT + j];
    c[j] += __logf(s);
}

__global__ void __launch_bounds__(256)
final_exp_kernel(float* __restrict__ S, const float* __restrict__ r,
                 const float* __restrict__ c)
{
    size_t idx = (size_t)blockIdx.x * blockDim.x + threadIdx.x;
    int row = (int)(idx >> 11);
    int j4 = (int)(idx & 2047);
    float4 s = ((const float4*)S)[idx];
    float rv = r[row];
    float4 cc = ((const float4*)c)[j4];
    s.x = __expf(s.x - rv - cc.x);
    s.y = __expf(s.y - rv - cc.y);
    s.z = __expf(s.z - rv - cc.z);
    s.w = __expf(s.w - rv - cc.w);
    ((float4*)S)[idx] = s;
}

// ---------------- launch ----------------
extern "C" void kernel_launch(void* const* d_in, const int* in_sizes, int n_in,
                              void* d_out, int out_size)
{
    const float* emb_a = (const float*)d_in[0];
    const float* emb_b = (const float*)d_in[1];
    const float* W1    = (const float*)d_in[2];
    const float* b1    = (const float*)d_in[3];
    const float* W2    = (const float*)d_in[4];
    const float* b2    = (const float*)d_in[5];
    float* out = (float*)d_out;

    float *r, *c, *cz, *p;
    float2* p2;
    fp16 *e1, *e2, *t1, *t2, *a1, *a2, *bb1, *bb2;
    fp16 *w1a, *w1b, *w2a, *w2b;
    cudaGetSymbolAddress((void**)&r, g_r);
    cudaGetSymbolAddress((void**)&c, g_c);
    cudaGetSymbolAddress((void**)&cz, g_cz);
    cudaGetSymbolAddress((void**)&p, g_p);
    cudaGetSymbolAddress((void**)&p2, g_p2);
    cudaGetSymbolAddress((void**)&e1, g_e1);
    cudaGetSymbolAddress((void**)&e2, g_e2);
    cudaGetSymbolAddress((void**)&t1, g_t1);
    cudaGetSymbolAddress((void**)&t2, g_t2);
    cudaGetSymbolAddress((void**)&a1, g_a1);
    cudaGetSymbolAddress((void**)&a2, g_a2);
    cudaGetSymbolAddress((void**)&bb1, g_b1);
    cudaGetSymbolAddress((void**)&bb2, g_b2);
    cudaGetSymbolAddress((void**)&w1a, g_w1a);
    cudaGetSymbolAddress((void**)&w1b, g_w1b);
    cudaGetSymbolAddress((void**)&w2a, g_w2a);
    cudaGetSymbolAddress((void**)&w2b, g_w2b);

    cudaFuncSetAttribute(mma_gemm<EPI_SCORE>,
                         cudaFuncAttributeMaxDynamicSharedMemorySize, MM_SMEM);
    cudaFuncSetAttribute(mma_gemm<EPI_GELU>,
                         cudaFuncAttributeMaxDynamicSharedMemorySize, MM_SMEM);
    cudaFuncSetAttribute(mma_gemm<EPI_BIAS>,
                         cudaFuncAttributeMaxDynamicSharedMemorySize, MM_SMEM);

    dim3 blk(256);
    dim3 tblk(32, 8);
    dim3 tgrid(DD / 32, DD / 32);
    dim3 grid_mlp(DD / 128, NT / 128);   // (8, 64)
    dim3 grid_big(NT / 128, NT / 128);   // (64, 64)
    unsigned nsplit = (unsigned)((size_t)NT * DD / 4 / 256);

    // weight transpose + split (once)
    tsplit<<<tgrid, tblk>>>(W1, w1a, w1b);
    tsplit<<<tgrid, tblk>>>(W2, w2a, w2b);

    // ---- projection of emb_a ----
    split2<<<nsplit, blk>>>(emb_a, e1, e2);
    mma_gemm<EPI_GELU><<<grid_mlp, blk, MM_SMEM>>>(
        e1, e2, w1a, w1b, b1, nullptr, t1, t2, DD);
    mma_gemm<EPI_BIAS><<<grid_mlp, blk, MM_SMEM>>>(
        t1, t2, w2a, w2b, b2, nullptr, a1, a2, DD);

    // ---- projection of emb_b ----
    split2<<<nsplit, blk>>>(emb_b, e1, e2);
    mma_gemm<EPI_GELU><<<grid_mlp, blk, MM_SMEM>>>(
        e1, e2, w1a, w1b, b1, nullptr, t1, t2, DD);
    mma_gemm<EPI_BIAS><<<grid_mlp, blk, MM_SMEM>>>(
        t1, t2, w2a, w2b, b2, nullptr, bb1, bb2, DD);

    // ---- scores = (a @ b^T) * 20 ----
    mma_gemm<EPI_SCORE><<<grid_big, blk, MM_SMEM>>>(
        a1, a2, bb1, bb2, nullptr, out, nullptr, nullptr, NT);

    // ---- Sinkhorn iteration 1 (exact, overflow-safe) ----
    zero_vec<<<NT / 256, blk>>>(cz);
    row_lse_kernel<<<NT, blk>>>(out, cz, r);
    col_lse_partial_kernel<<<dim3((NT / 4) / 256, CSPLIT), blk>>>(out, r, p2);
    col_lse_combine_kernel<<<NT / 256, blk>>>(p2, c);

    // ---- iterations 2..20: fused fast path ----
    for (int it = 0; it < 19; it++) {
        sink_fast<<<CH, blk>>>(out, r, c, p);
        comb_add<<<NT / 256, blk>>>(p, c);
    }

    final_exp_kernel<<<(unsigned)((size_t)NT * NT / 4 / 256), blk>>>(out, r, c);
}

// round 10
// speedup vs baseline: 4.8432x; 1.0304x over previous
#include <cuda_runtime.h>
#include <cuda_fp16.h>
#include <math.h>
#include <stdint.h>

#define NT 8192
#define DD 1024
#define CSPLIT 128        // iter-1 column-partial chunks
#define CH 512            // fast-iter row chunks
#define RPC (NT / CH)     // 16 rows per chunk

typedef __half fp16;

// ---------------- scratch (device globals) ----------------
__device__ fp16 g_e1[(size_t)NT * DD], g_e2[(size_t)NT * DD];
__device__ fp16 g_t1[(size_t)NT * DD], g_t2[(size_t)NT * DD];
__device__ fp16 g_a1[(size_t)NT * DD], g_a2[(size_t)NT * DD];
__device__ fp16 g_b1[(size_t)NT * DD], g_b2[(size_t)NT * DD];
__device__ fp16 g_w1a[(size_t)DD * DD], g_w1b[(size_t)DD * DD];
__device__ fp16 g_w2a[(size_t)DD * DD], g_w2b[(size_t)DD * DD];
__device__ float  g_r[NT];
__device__ float  g_c[NT];
__device__ float  g_cz[NT];
__device__ float  g_p[(size_t)CH * NT];
__device__ float2 g_p2[(size_t)CSPLIT * NT];

// ---------------- small helpers ----------------
__device__ __forceinline__ uint32_t smem_u32(const void* p) {
    uint32_t a;
    asm("{ .reg .u64 t; cvta.to.shared.u64 t, %1; cvt.u32.u64 %0, t; }"
        : "=r"(a) : "l"(p));
    return a;
}
__device__ __forceinline__ void cp16(uint32_t dst, const void* src) {
    asm volatile("cp.async.ca.shared.global [%0], [%1], 16;"
                 :: "r"(dst), "l"(src) : "memory");
}
__device__ __forceinline__ void cp_commit() {
    asm volatile("cp.async.commit_group;" ::: "memory");
}
template <int N>
__device__ __forceinline__ void cp_wait() {
    asm volatile("cp.async.wait_group %0;" :: "n"(N) : "memory");
}
__device__ __forceinline__ void ldsm4(uint32_t& r0, uint32_t& r1,
                                      uint32_t& r2, uint32_t& r3, uint32_t a) {
    asm volatile("ldmatrix.sync.aligned.m8n8.x4.shared.b16 {%0,%1,%2,%3}, [%4];"
                 : "=r"(r0), "=r"(r1), "=r"(r2), "=r"(r3) : "r"(a));
}
__device__ __forceinline__ void mma16816(float* d, const uint32_t* a,
                                         const uint32_t* b) {
    asm volatile(
        "mma.sync.aligned.m16n8k16.row.col.f32.f16.f16.f32 "
        "{%0,%1,%2,%3}, {%4,%5,%6,%7}, {%8,%9}, {%0,%1,%2,%3};"
        : "+f"(d[0]), "+f"(d[1]), "+f"(d[2]), "+f"(d[3])
        : "r"(a[0]), "r"(a[1]), "r"(a[2]), "r"(a[3]), "r"(b[0]), "r"(b[1]));
}

__device__ __forceinline__ void split1(float v, fp16& h1, fp16& h2)
{
    h1 = __float2half_rn(v);
    h2 = __float2half_rn(v - __half2float(h1));
}

// ================= fp16x2 split of a full fp32 array =================
__global__ void __launch_bounds__(256)
split2(const float* __restrict__ x, fp16* __restrict__ o1,
       fp16* __restrict__ o2)
{
    size_t i4 = (size_t)blockIdx.x * 256 + threadIdx.x;
    float4 v = ((const float4*)x)[i4];
    float vv[4] = {v.x, v.y, v.z, v.w};
    fp16 e1[4], e2[4];
#pragma unroll
    for (int k = 0; k < 4; k++) split1(vv[k], e1[k], e2[k]);
    ((uint2*)o1)[i4] = *(uint2*)e1;
    ((uint2*)o2)[i4] = *(uint2*)e2;
}

// ================= transpose + split W [K,N] -> Wt splits [N,K] ============
__global__ void __launch_bounds__(256)
tsplit(const float* __restrict__ W, fp16* __restrict__ o1,
       fp16* __restrict__ o2)
{
    __shared__ float tile[32][33];
    const int bn = blockIdx.x * 32;
    const int bk = blockIdx.y * 32;
    const int tx = threadIdx.x, ty = threadIdx.y;   // 32 x 8
#pragma unroll
    for (int i = 0; i < 32; i += 8)
        tile[ty + i][tx] = W[(size_t)(bk + ty + i) * DD + bn + tx];
    __syncthreads();
#pragma unroll
    for (int i = 0; i < 32; i += 8) {
        float v = tile[tx][ty + i];
        fp16 h1, h2;
        split1(v, h1, h2);
        size_t off = (size_t)(bn + ty + i) * DD + bk + tx;
        o1[off] = h1; o2[off] = h2;
    }
}

// ================= mma.sync fp16x3-pair GEMM: acc = A · B^T ================
// CTA tile 128(M) x 256(N), warp tile 64x64, BK=32, 3-stage cp.async pipeline.
#define BKC 32
#define AST 40                  // padded smem stride (fp16); 80 B, 16B-aligned
#define NCHK (DD / BKC)         // 32
#define NSTG 3
// stage layout (fp16 offsets): A1(128 rows), A2(128), B1(256), B2(256)
#define STG_FP16 (768 * AST)    // 30720 fp16 = 61440 B
#define OFF_A1 0
#define OFF_A2 (128 * AST)
#define OFF_B1 (256 * AST)
#define OFF_B2 (512 * AST)
#define MM_SMEM (NSTG * STG_FP16 * 2)   // 184320 bytes

enum { EPI_SCORE = 0, EPI_GELU = 1, EPI_BIAS = 2 };

template <int EPI>
__global__ void __launch_bounds__(256, 1)
mma_gemm(const fp16* __restrict__ A1, const fp16* __restrict__ A2,
         const fp16* __restrict__ B1, const fp16* __restrict__ B2,
         const float* __restrict__ bias, float* __restrict__ Cf,
         fp16* __restrict__ O1, fp16* __restrict__ O2, int ldc)
{
    extern __shared__ __align__(16) fp16 sm[];
    const uint32_t sS = smem_u32(sm);
    const int tid = threadIdx.x;
    const int wid = tid >> 5, lane = tid & 31;
    const int bm = blockIdx.y * 128, bn = blockIdx.x * 256;
    const int wm = (wid & 1) * 64, wn = (wid >> 1) * 64;

    const fp16* srcA1 = A1 + (size_t)bm * DD;
    const fp16* srcA2 = A2 + (size_t)bm * DD;
    const fp16* srcB1 = B1 + (size_t)bn * DD;
    const fp16* srcB2 = B2 + (size_t)bn * DD;

    float acc[4][8][4];
#pragma unroll
    for (int i = 0; i < 4; i++)
#pragma unroll
        for (int j = 0; j < 8; j++)
#pragma unroll
            for (int k = 0; k < 4; k++) acc[i][j][k] = 0.0f;

    const int lrow = tid >> 2;         // 0..63
    const int lseg = (tid & 3) * 8;    // fp16 offset 0,8,16,24

    auto load_chunk = [&](int stage, int k0) {
        const uint32_t so = (uint32_t)(stage * STG_FP16);
        // A tiles: 128 rows each, 2 passes of 64 rows
#pragma unroll
        for (int p = 0; p < 2; p++) {
            int row = lrow + p * 64;
            cp16(sS + (so + (uint32_t)(OFF_A1 + row * AST + lseg)) * 2,
                 srcA1 + (size_t)row * DD + k0 + lseg);
            cp16(sS + (so + (uint32_t)(OFF_A2 + row * AST + lseg)) * 2,
                 srcA2 + (size_t)row * DD + k0 + lseg);
        }
        // B tiles: 256 rows each, 4 passes of 64 rows
#pragma unroll
        for (int p = 0; p < 4; p++) {
            int row = lrow + p * 64;
            cp16(sS + (so + (uint32_t)(OFF_B1 + row * AST + lseg)) * 2,
                 srcB1 + (size_t)row * DD + k0 + lseg);
            cp16(sS + (so + (uint32_t)(OFF_B2 + row * AST + lseg)) * 2,
                 srcB2 + (size_t)row * DD + k0 + lseg);
        }
    };

    // prefetch chunks 0,1
    load_chunk(0, 0);
    cp_commit();
    load_chunk(1, BKC);
    cp_commit();

    for (int ch = 0; ch < NCHK; ch++) {
        if (ch < NCHK - 1) cp_wait<1>(); else cp_wait<0>();
        __syncthreads();
        if (ch + 2 < NCHK) {
            load_chunk((ch + 2) % NSTG, (ch + 2) * BKC);
            cp_commit();
        }

        const uint32_t bo = (uint32_t)((ch % NSTG) * STG_FP16);
#pragma unroll
        for (int kt = 0; kt < 2; kt++) {
            // A fragments: 2 splits x 4 m-tiles (A1 reused by 2 products)
            uint32_t afA[2][4][4];
#pragma unroll
            for (int mt = 0; mt < 4; mt++) {
                uint32_t ra = (uint32_t)((wm + mt * 16 + (lane & 15)) * AST +
                                         kt * 16 + (lane >> 4) * 8);
                ldsm4(afA[0][mt][0], afA[0][mt][1], afA[0][mt][2],
                      afA[0][mt][3], sS + (bo + OFF_A1 + ra) * 2);
                ldsm4(afA[1][mt][0], afA[1][mt][1], afA[1][mt][2],
                      afA[1][mt][3], sS + (bo + OFF_A2 + ra) * 2);
            }
            // B in 16-col groups; B fragments short-lived per np
#pragma unroll
            for (int np = 0; np < 4; np++) {
                uint32_t rb = (uint32_t)((wn + np * 16 + (lane & 7) +
                                          ((lane >> 4) << 3)) * AST +
                                         kt * 16 + ((lane >> 3) & 1) * 8);
                uint32_t b1f[4], b2f[4];
                ldsm4(b1f[0], b1f[1], b1f[2], b1f[3],
                      sS + (bo + OFF_B1 + rb) * 2);
                ldsm4(b2f[0], b2f[1], b2f[2], b2f[3],
                      sS + (bo + OFF_B2 + rb) * 2);
#pragma unroll
                for (int half = 0; half < 2; half++) {
                    int nt = np * 2 + half;
                    uint32_t b1v[2] = {b1f[half * 2], b1f[half * 2 + 1]};
                    uint32_t b2v[2] = {b2f[half * 2], b2f[half * 2 + 1]};
#pragma unroll
                    for (int mt = 0; mt < 4; mt++) {
                        mma16816(acc[mt][nt], afA[0][mt], b1v);
                        mma16816(acc[mt][nt], afA[0][mt], b2v);
                        mma16816(acc[mt][nt], afA[1][mt], b1v);
                    }
                }
            }
        }
    }

    // epilogue
#pragma unroll
    for (int mt = 0; mt < 4; mt++) {
#pragma unroll
        for (int nt = 0; nt < 8; nt++) {
            int row = bm + wm + mt * 16 + (lane >> 2);
            int col = bn + wn + nt * 8 + (lane & 3) * 2;
            float* d = acc[mt][nt];
            if (EPI == EPI_SCORE) {
                *(float2*)&Cf[(size_t)row * ldc + col] =
                    make_float2(d[0] * 20.0f, d[1] * 20.0f);
                *(float2*)&Cf[(size_t)(row + 8) * ldc + col] =
                    make_float2(d[2] * 20.0f, d[3] * 20.0f);
            } else {
                float bx = bias[col], by = bias[col + 1];
                float v[4] = {d[0] + bx, d[1] + by, d[2] + bx, d[3] + by};
                if (EPI == EPI_GELU) {
#pragma unroll
                    for (int k = 0; k < 4; k++)
                        v[k] = 0.5f * v[k] *
                               (1.0f + erff(v[k] * 0.70710678118654752f));
                }
#pragma unroll
                for (int h = 0; h < 2; h++) {
                    fp16 s1[2], s2[2];
                    split1(v[2 * h + 0], s1[0], s2[0]);
                    split1(v[2 * h + 1], s1[1], s2[1]);
                    size_t off = (size_t)(row + 8 * h) * ldc + col;
                    *(uint32_t*)(O1 + off) = *(uint32_t*)s1;
                    *(uint32_t*)(O2 + off) = *(uint32_t*)s2;
                }
            }
        }
    }
}

// ================= Sinkhorn (R5-R8 proven) =================
__device__ __forceinline__ void lse_upd(float& m, float& l, float v)
{
    if (v <= m) {
        l += __expf(v - m);
    } else {
        l = fmaf(l, __expf(m - v), 1.0f);
        m = v;
    }
}

__global__ void zero_vec(float* __restrict__ c)
{
    c[blockIdx.x * 256 + threadIdx.x] = 0.0f;
}

__global__ void __launch_bounds__(256)
row_lse_kernel(const float* __restrict__ S, const float* __restrict__ c,
               float* __restrict__ r)
{
    const int row = blockIdx.x;
    const int tid = threadIdx.x;
    const float4* s4 = (const float4*)(S + (size_t)row * NT);
    const float4* c4 = (const float4*)c;

    float m = -INFINITY, l = 0.0f;
    for (int j = tid; j < NT / 4; j += 256) {
        float4 s = s4[j];
        float4 cc = c4[j];
        lse_upd(m, l, s.x - cc.x);
        lse_upd(m, l, s.y - cc.y);
        lse_upd(m, l, s.z - cc.z);
        lse_upd(m, l, s.w - cc.w);
    }

    __shared__ float sm[256], sl[256];
    sm[tid] = m; sl[tid] = l;
    __syncthreads();
    for (int s = 128; s > 0; s >>= 1) {
        if (tid < s) {
            float m2 = sm[tid + s], l2 = sl[tid + s];
            float nm = fmaxf(sm[tid], m2);
            sl[tid] = sl[tid] * __expf(sm[tid] - nm) + l2 * __expf(m2 - nm);
            sm[tid] = nm;
        }
        __syncthreads();
    }
    if (tid == 0) r[row] = sm[0] + __logf(sl[0]);
}

__global__ void __launch_bounds__(256)
col_lse_partial_kernel(const float* __restrict__ S, const float* __restrict__ r,
                       float2* __restrict__ part)
{
    const int j4 = blockIdx.x * blockDim.x + threadIdx.x;
    const int chunk = blockIdx.y;
    const int rowsPer = NT / CSPLIT;
    const int i0 = chunk * rowsPer;

    float m0 = -INFINITY, m1 = -INFINITY, m2 = -INFINITY, m3 = -INFINITY;
    float l0 = 0.f, l1 = 0.f, l2 = 0.f, l3 = 0.f;

    const float4* S4 = (const float4*)S;
    for (int i = i0; i < i0 + rowsPer; i++) {
        float4 s = S4[(size_t)i * (NT / 4) + j4];
        float rv = __ldg(&r[i]);
        lse_upd(m0, l0, s.x - rv);
        lse_upd(m1, l1, s.y - rv);
        lse_upd(m2, l2, s.z - rv);
        lse_upd(m3, l3, s.w - rv);
    }
    int j = j4 * 4;
    float2* p = part + (size_t)chunk * NT + j;
    p[0] = make_float2(m0, l0);
    p[1] = make_float2(m1, l1);
    p[2] = make_float2(m2, l2);
    p[3] = make_float2(m3, l3);
}

__global__ void __launch_bounds__(256)
col_lse_combine_kernel(const float2* __restrict__ part, float* __restrict__ c)
{
    const int j = blockIdx.x * blockDim.x + threadIdx.x;
    float m = -INFINITY, l = 0.0f;
    for (int k = 0; k < CSPLIT; k++) {
        float2 p = part[(size_t)k * NT + j];
        float nm = fmaxf(m, p.x);
        l = l * __expf(m - nm) + p.y * __expf(p.x - nm);
        m = nm;
    }
    c[j] = m + __logf(l);
}

__device__ __forceinline__ float blk_sum(float x, float* sb, int tid)
{
#pragma unroll
    for (int o = 16; o; o >>= 1) x += __shfl_down_sync(0xffffffffu, x, o);
    if ((tid & 31) == 0) sb[tid >> 5] = x;
    __syncthreads();
    if (tid < 32) {
        float y = (tid < 8) ? sb[tid] : 0.0f;
#pragma unroll
        for (int o = 4; o; o >>= 1) y += __shfl_down_sync(0xffffffffu, y, o);
        if (tid == 0) sb[32] = y;
    }
    __syncthreads();
    float r = sb[32];
    __syncthreads();
    return r;
}

__global__ void __launch_bounds__(256)
sink_fast(const float* __restrict__ S, float* __restrict__ r,
          const float* __restrict__ c, float* __restrict__ part)
{
    __shared__ float cc[NT];
    __shared__ float sb[40];
    const int tid = threadIdx.x, chunk = blockIdx.x;

    for (int k = tid; k < NT / 4; k += 256)
        ((float4*)cc)[k] = ((const float4*)c)[k];
    __syncthreads();

    float acc[32];
#pragma unroll
    for (int k = 0; k < 32; k++) acc[k] = 0.0f;

    for (int i = chunk * RPC; i < chunk * RPC + RPC; i++) {
        const float4* S4 = (const float4*)(S + (size_t)i * NT);
        const float rr = r[i];
        float4 e[8];
        float dot = 0.0f;
#pragma unroll
        for (int q = 0; q < 8; q++) {
            float4 s = S4[tid + 256 * q];
            float4 cv = *(const float4*)&cc[4 * (tid + 256 * q)];
            e[q].x = __expf(s.x - cv.x - rr);
            e[q].y = __expf(s.y - cv.y - rr);
            e[q].z = __expf(s.z - cv.z - rr);
            e[q].w = __expf(s.w - cv.w - rr);
            dot += (e[q].x + e[q].y) + (e[q].z + e[q].w);
        }
        dot = blk_sum(dot, sb, tid);
        float w = __fdividef(1.0f, dot);
        if (tid == 0) r[i] = rr + __logf(dot);
#pragma unroll
        for (int q = 0; q < 8; q++) {
            acc[4 * q + 0] = fmaf(e[q].x, w, acc[4 * q + 0]);
            acc[4 * q + 1] = fmaf(e[q].y, w, acc[4 * q + 1]);
            acc[4 * q + 2] = fmaf(e[q].z, w, acc[4 * q + 2]);
            acc[4 * q + 3] = fmaf(e[q].w, w, acc[4 * q + 3]);
        }
    }
    float* pp = part + (size_t)chunk * NT;
#pragma unroll
    for (int q = 0; q < 8; q++) {
        int j = 4 * (tid + 256 * q);
        *(float4*)&pp[j] = make_float4(acc[4 * q + 0], acc[4 * q + 1],
                                       acc[4 * q + 2], acc[4 * q + 3]);
    }
}

__global__ void __launch_bounds__(256)
comb_add(const float* __restrict__ part, float* __restrict__ c)
{
    const int j = blockIdx.x * 256 + threadIdx.x;
    float s = 0.0f;
    for (int k = 0; k < CH; k++) s += part[(size_t)k * NT + j];
    c[j] += __logf(s);
}

__global__ void __launch_bounds__(256)
final_exp_kernel(float* __restrict__ S, const float* __restrict__ r,
                 const float* __restrict__ c)
{
    size_t idx = (size_t)blockIdx.x * blockDim.x + threadIdx.x;
    int row = (int)(idx >> 11);
    int j4 = (int)(idx & 2047);
    float4 s = ((const float4*)S)[idx];
    float rv = r[row];
    float4 cc = ((const float4*)c)[j4];
    s.x = __expf(s.x - rv - cc.x);
    s.y = __expf(s.y - rv - cc.y);
    s.z = __expf(s.z - rv - cc.z);
    s.w = __expf(s.w - rv - cc.w);
    ((float4*)S)[idx] = s;
}

// ---------------- launch ----------------
extern "C" void kernel_launch(void* const* d_in, const int* in_sizes, int n_in,
                              void* d_out, int out_size)
{
    const float* emb_a = (const float*)d_in[0];
    const float* emb_b = (const float*)d_in[1];
    const float* W1    = (const float*)d_in[2];
    const float* b1    = (const float*)d_in[3];
    const float* W2    = (const float*)d_in[4];
    const float* b2    = (const float*)d_in[5];
    float* out = (float*)d_out;

    float *r, *c, *cz, *p;
    float2* p2;
    fp16 *e1, *e2, *t1, *t2, *a1, *a2, *bb1, *bb2;
    fp16 *w1a, *w1b, *w2a, *w2b;
    cudaGetSymbolAddress((void**)&r, g_r);
    cudaGetSymbolAddress((void**)&c, g_c);
    cudaGetSymbolAddress((void**)&cz, g_cz);
    cudaGetSymbolAddress((void**)&p, g_p);
    cudaGetSymbolAddress((void**)&p2, g_p2);
    cudaGetSymbolAddress((void**)&e1, g_e1);
    cudaGetSymbolAddress((void**)&e2, g_e2);
    cudaGetSymbolAddress((void**)&t1, g_t1);
    cudaGetSymbolAddress((void**)&t2, g_t2);
    cudaGetSymbolAddress((void**)&a1, g_a1);
    cudaGetSymbolAddress((void**)&a2, g_a2);
    cudaGetSymbolAddress((void**)&bb1, g_b1);
    cudaGetSymbolAddress((void**)&bb2, g_b2);
    cudaGetSymbolAddress((void**)&w1a, g_w1a);
    cudaGetSymbolAddress((void**)&w1b, g_w1b);
    cudaGetSymbolAddress((void**)&w2a, g_w2a);
    cudaGetSymbolAddress((void**)&w2b, g_w2b);

    cudaFuncSetAttribute(mma_gemm<EPI_SCORE>,
                         cudaFuncAttributeMaxDynamicSharedMemorySize, MM_SMEM);
    cudaFuncSetAttribute(mma_gemm<EPI_GELU>,
                         cudaFuncAttributeMaxDynamicSharedMemorySize, MM_SMEM);
    cudaFuncSetAttribute(mma_gemm<EPI_BIAS>,
                         cudaFuncAttributeMaxDynamicSharedMemorySize, MM_SMEM);

    dim3 blk(256);
    dim3 tblk(32, 8);
    dim3 tgrid(DD / 32, DD / 32);
    dim3 grid_mlp(DD / 256, NT / 128);   // (4, 64)
    dim3 grid_big(NT / 256, NT / 128);   // (32, 64)
    unsigned nsplit = (unsigned)((size_t)NT * DD / 4 / 256);

    // weight transpose + split (once)
    tsplit<<<tgrid, tblk>>>(W1, w1a, w1b);
    tsplit<<<tgrid, tblk>>>(W2, w2a, w2b);

    // ---- projection of emb_a ----
    split2<<<nsplit, blk>>>(emb_a, e1, e2);
    mma_gemm<EPI_GELU><<<grid_mlp, blk, MM_SMEM>>>(
        e1, e2, w1a, w1b, b1, nullptr, t1, t2, DD);
    mma_gemm<EPI_BIAS><<<grid_mlp, blk, MM_SMEM>>>(
        t1, t2, w2a, w2b, b2, nullptr, a1, a2, DD);

    // ---- projection of emb_b ----
    split2<<<nsplit, blk>>>(emb_b, e1, e2);
    mma_gemm<EPI_GELU><<<grid_mlp, blk, MM_SMEM>>>(
        e1, e2, w1a, w1b, b1, nullptr, t1, t2, DD);
    mma_gemm<EPI_BIAS><<<grid_mlp, blk, MM_SMEM>>>(
        t1, t2, w2a, w2b, b2, nullptr, bb1, bb2, DD);

    // ---- scores = (a @ b^T) * 20 ----
    mma_gemm<EPI_SCORE><<<grid_big, blk, MM_SMEM>>>(
        a1, a2, bb1, bb2, nullptr, out, nullptr, nullptr, NT);

    // ---- Sinkhorn iteration 1 (exact, overflow-safe) ----
    zero_vec<<<NT / 256, blk>>>(cz);
    row_lse_kernel<<<NT, blk>>>(out, cz, r);
    col_lse_partial_kernel<<<dim3((NT / 4) / 256, CSPLIT), blk>>>(out, r, p2);
    col_lse_combine_kernel<<<NT / 256, blk>>>(p2, c);

    // ---- iterations 2..20: fused fast path ----
    for (int it = 0; it < 19; it++) {
        sink_fast<<<CH, blk>>>(out, r, c, p);
        comb_add<<<NT / 256, blk>>>(p, c);
    }

    final_exp_kernel<<<(unsigned)((size_t)NT * NT / 4 / 256), blk>>>(out, r, c);
}